// round 2
// baseline (speedup 1.0000x reference)
#include <cuda_runtime.h>
#include <cuda_bf16.h>
#include <math.h>

// Problem constants
#define BATCH 8
#define CH    512
#define NN    1024         // H*W
#define NH    8
#define HD    64
#define GRP   8
#define CPG   64           // channels per group
#define GN_EPS 1e-5f

// Scratch (device globals: allocation-free rule)
__device__ float g_qkv[(size_t)BATCH * 3 * CH * NN];   // [B,3,nh,hd,N] = [B,1536,1024]
__device__ float g_att[(size_t)BATCH * CH * NN];       // [B,512,1024]
__device__ float g_proj[(size_t)BATCH * CH * NN];      // [B,512,1024]

// ---------------------------------------------------------------------------
// Tiled SGEMM: C[b] = A (MxK, shared over batch) * B[b] (KxN), all row-major.
// BM=BN=128, BK=8, 256 threads, 8x8 micro-tile per thread.
// Grid: (N/128, M/128, batch)
// ---------------------------------------------------------------------------
__global__ __launch_bounds__(256) void sgemm128(
    const float* __restrict__ A, const float* __restrict__ Bg,
    float* __restrict__ Cg, int M, int N, int K)
{
    const int bz = blockIdx.z;
    const float* Bp = Bg + (size_t)bz * K * N;
    float*       Cp = Cg + (size_t)bz * M * N;

    __shared__ float As[8][128];
    __shared__ float Bs[8][128];

    const int tid = threadIdx.x;
    const int tx = tid & 15;        // 0..15 (N direction)
    const int ty = tid >> 4;        // 0..15 (M direction)
    const int row0 = blockIdx.y * 128;
    const int col0 = blockIdx.x * 128;

    // load mapping
    const int arow  = tid >> 1;          // 0..127
    const int acol4 = (tid & 1) * 4;     // 0 or 4
    const int brow  = tid >> 5;          // 0..7
    const int bcol4 = (tid & 31) * 4;    // 0..124

    float acc[8][8];
    #pragma unroll
    for (int i = 0; i < 8; i++)
        #pragma unroll
        for (int j = 0; j < 8; j++) acc[i][j] = 0.f;

    for (int kk = 0; kk < K; kk += 8) {
        float4 av = *(const float4*)&A[(size_t)(row0 + arow) * K + kk + acol4];
        As[acol4 + 0][arow] = av.x;
        As[acol4 + 1][arow] = av.y;
        As[acol4 + 2][arow] = av.z;
        As[acol4 + 3][arow] = av.w;
        float4 bv = *(const float4*)&Bp[(size_t)(kk + brow) * N + col0 + bcol4];
        *(float4*)&Bs[brow][bcol4] = bv;
        __syncthreads();

        #pragma unroll
        for (int k = 0; k < 8; k++) {
            float a[8], b[8];
            *(float4*)&a[0] = *(const float4*)&As[k][ty * 8];
            *(float4*)&a[4] = *(const float4*)&As[k][ty * 8 + 4];
            *(float4*)&b[0] = *(const float4*)&Bs[k][tx * 8];
            *(float4*)&b[4] = *(const float4*)&Bs[k][tx * 8 + 4];
            #pragma unroll
            for (int i = 0; i < 8; i++)
                #pragma unroll
                for (int j = 0; j < 8; j++)
                    acc[i][j] += a[i] * b[j];
        }
        __syncthreads();
    }

    #pragma unroll
    for (int i = 0; i < 8; i++) {
        float* crow = &Cp[(size_t)(row0 + ty * 8 + i) * N + col0 + tx * 8];
        *(float4*)&crow[0] = make_float4(acc[i][0], acc[i][1], acc[i][2], acc[i][3]);
        *(float4*)&crow[4] = make_float4(acc[i][4], acc[i][5], acc[i][6], acc[i][7]);
    }
}

// ---------------------------------------------------------------------------
// Flash-style attention. One thread per query row (n). Block = 128 threads,
// handles 128 rows for one (b,h). Grid: (N/128, nh, B).
// q/k/v layout inside g_qkv: [B, 3, nh, hd, N]
// Output layout: [B, C, N] with channel = h*HD + d
// ---------------------------------------------------------------------------
__global__ __launch_bounds__(128) void attn_kernel(
    const float* __restrict__ qkv, float* __restrict__ out)
{
    const int b = blockIdx.z;
    const int h = blockIdx.y;
    const int n = blockIdx.x * 128 + threadIdx.x;

    const float* q = qkv + (((size_t)b * 3 + 0) * NH + h) * HD * NN;
    const float* k = qkv + (((size_t)b * 3 + 1) * NH + h) * HD * NN;
    const float* v = qkv + (((size_t)b * 3 + 2) * NH + h) * HD * NN;

    __shared__ float ks[HD * 64];
    __shared__ float vs[HD * 64];

    const float scale = 0.125f;   // hd^-0.5 = 1/8

    float qr[HD];
    #pragma unroll
    for (int d = 0; d < HD; d++) qr[d] = q[(size_t)d * NN + n] * scale;

    float o[HD];
    #pragma unroll
    for (int d = 0; d < HD; d++) o[d] = 0.f;

    float Mx = -1e30f, L = 0.f;

    for (int mt = 0; mt < NN / 64; mt++) {
        const int m0 = mt * 64;
        __syncthreads();
        #pragma unroll
        for (int i = 0; i < 32; i++) {
            int idx = threadIdx.x + i * 128;
            int d = idx >> 6, mm = idx & 63;
            ks[idx] = k[(size_t)d * NN + m0 + mm];
            vs[idx] = v[(size_t)d * NN + m0 + mm];
        }
        __syncthreads();

        float s[64];
        #pragma unroll
        for (int m = 0; m < 64; m++) s[m] = 0.f;

        #pragma unroll
        for (int d = 0; d < HD; d++) {
            float qd = qr[d];
            const float4* kr = (const float4*)&ks[d * 64];
            #pragma unroll
            for (int m4 = 0; m4 < 16; m4++) {
                float4 kv = kr[m4];
                s[m4 * 4 + 0] += qd * kv.x;
                s[m4 * 4 + 1] += qd * kv.y;
                s[m4 * 4 + 2] += qd * kv.z;
                s[m4 * 4 + 3] += qd * kv.w;
            }
        }

        float tm = s[0];
        #pragma unroll
        for (int m = 1; m < 64; m++) tm = fmaxf(tm, s[m]);
        float nM = fmaxf(Mx, tm);
        float corr = __expf(Mx - nM);

        float ls = 0.f;
        #pragma unroll
        for (int m = 0; m < 64; m++) {
            s[m] = __expf(s[m] - nM);
            ls += s[m];
        }
        L = L * corr + ls;

        #pragma unroll
        for (int d = 0; d < HD; d++) {
            float acc = o[d] * corr;
            const float4* vr = (const float4*)&vs[d * 64];
            #pragma unroll
            for (int m4 = 0; m4 < 16; m4++) {
                float4 vv = vr[m4];
                acc += s[m4 * 4 + 0] * vv.x;
                acc += s[m4 * 4 + 1] * vv.y;
                acc += s[m4 * 4 + 2] * vv.z;
                acc += s[m4 * 4 + 3] * vv.w;
            }
            o[d] = acc;
        }
        Mx = nM;
    }

    const float inv = 1.f / L;
    #pragma unroll
    for (int d = 0; d < HD; d++)
        out[((size_t)b * CH + h * HD + d) * NN + n] = o[d] * inv;
}

// ---------------------------------------------------------------------------
// GroupNorm(affine) + residual.  One block per (b,g). 512 threads.
// group = 64 channels x 1024 spatial = 65536 elems = 16384 float4.
// ---------------------------------------------------------------------------
__global__ __launch_bounds__(512) void gn_kernel(
    const float* __restrict__ pin, const float* __restrict__ x,
    const float* __restrict__ gamma, const float* __restrict__ beta,
    float* __restrict__ out)
{
    const int b = blockIdx.x >> 3;
    const int g = blockIdx.x & 7;
    const size_t base = ((size_t)b * CH + g * CPG) * NN;   // floats
    const float4* p4 = (const float4*)(pin + base);
    const float4* x4 = (const float4*)(x + base);
    float4*       o4 = (float4*)(out + base);

    const int tid = threadIdx.x;
    float sum = 0.f, ss = 0.f;
    for (int i = tid; i < 16384; i += 512) {
        float4 p = p4[i];
        sum += p.x + p.y + p.z + p.w;
        ss  += p.x * p.x + p.y * p.y + p.z * p.z + p.w * p.w;
    }
    // block reduce
    #pragma unroll
    for (int off = 16; off; off >>= 1) {
        sum += __shfl_xor_sync(0xffffffffu, sum, off);
        ss  += __shfl_xor_sync(0xffffffffu, ss, off);
    }
    __shared__ float reds[16], redq[16], stats[2];
    const int warp = tid >> 5, lane = tid & 31;
    if (lane == 0) { reds[warp] = sum; redq[warp] = ss; }
    __syncthreads();
    if (tid == 0) {
        float s = 0.f, q = 0.f;
        #pragma unroll
        for (int w = 0; w < 16; w++) { s += reds[w]; q += redq[w]; }
        const float invn = 1.f / 65536.f;
        float mean = s * invn;
        float var  = q * invn - mean * mean;
        stats[0] = mean;
        stats[1] = rsqrtf(var + GN_EPS);
    }
    __syncthreads();
    const float mean = stats[0], inv = stats[1];

    for (int i = tid; i < 16384; i += 512) {
        int c = g * CPG + (i >> 8);     // (i*4)/1024
        float ga = gamma[c], be = beta[c];
        float4 p = p4[i];
        float4 xv = x4[i];
        float4 r;
        r.x = (p.x - mean) * inv * ga + be + xv.x;
        r.y = (p.y - mean) * inv * ga + be + xv.y;
        r.z = (p.z - mean) * inv * ga + be + xv.z;
        r.w = (p.w - mean) * inv * ga + be + xv.w;
        o4[i] = r;
    }
}

// ---------------------------------------------------------------------------
extern "C" void kernel_launch(void* const* d_in, const int* in_sizes, int n_in,
                              void* d_out, int out_size)
{
    const float* x      = (const float*)d_in[0];   // [8,512,32,32]
    const float* w_qkv  = (const float*)d_in[1];   // [1536,512]
    const float* w_proj = (const float*)d_in[2];   // [512,512]
    const float* gamma  = (const float*)d_in[3];   // [512]
    const float* beta   = (const float*)d_in[4];   // [512]
    float* out = (float*)d_out;

    float* qkv;  cudaGetSymbolAddress((void**)&qkv,  g_qkv);
    float* att;  cudaGetSymbolAddress((void**)&att,  g_att);
    float* proj; cudaGetSymbolAddress((void**)&proj, g_proj);

    // 1) QKV projection: per batch, (1536x512) * (512x1024)
    sgemm128<<<dim3(NN / 128, (3 * CH) / 128, BATCH), 256>>>(
        w_qkv, x, qkv, 3 * CH, NN, CH);

    // 2) Attention per (b,h)
    attn_kernel<<<dim3(NN / 128, NH, BATCH), 128>>>(qkv, att);

    // 3) Output projection: per batch, (512x512) * (512x1024)
    sgemm128<<<dim3(NN / 128, CH / 128, BATCH), 256>>>(
        w_proj, att, proj, CH, NN, CH);

    // 4) GroupNorm + affine + residual
    gn_kernel<<<BATCH * GRP, 512>>>(proj, x, gamma, beta, out);
}

// round 3
// speedup vs baseline: 4.8538x; 4.8538x over previous
#include <cuda_runtime.h>
#include <cuda_bf16.h>
#include <math.h>

// Problem constants
#define BATCH 8
#define CH    512
#define NN    1024         // H*W
#define NH    8
#define HD    64
#define GRP   8
#define CPG   64
#define GN_EPS 1e-5f

// Scratch (device globals: allocation-free rule)
__device__ float g_qkv[(size_t)BATCH * 3 * CH * NN];   // [B,1536,1024]
__device__ float g_att[(size_t)BATCH * CH * NN];       // [B,512,1024]
__device__ float g_proj[(size_t)BATCH * CH * NN];      // [B,512,1024]

// ---------------------------------------------------------------------------
// tf32 helpers
// ---------------------------------------------------------------------------
__device__ __forceinline__ unsigned f2tf(float f) {
    unsigned r;
    asm("cvt.rna.tf32.f32 %0, %1;" : "=r"(r) : "f"(f));
    return r;
}
__device__ __forceinline__ float f2tf_f(float f) {
    return __uint_as_float(f2tf(f));
}
__device__ __forceinline__ void mma_tf32(float* c,
    unsigned a0, unsigned a1, unsigned a2, unsigned a3,
    unsigned b0, unsigned b1)
{
    asm volatile(
        "mma.sync.aligned.m16n8k8.row.col.f32.tf32.tf32.f32 "
        "{%0,%1,%2,%3}, {%4,%5,%6,%7}, {%8,%9}, {%0,%1,%2,%3};"
        : "+f"(c[0]), "+f"(c[1]), "+f"(c[2]), "+f"(c[3])
        : "r"(a0), "r"(a1), "r"(a2), "r"(a3), "r"(b0), "r"(b1));
}

// ---------------------------------------------------------------------------
// tf32 MMA GEMM: C[bz] (MxN) = A (MxK, shared) * B[bz] (KxN), row-major.
// Block 128x128, 8 warps (4x2), warp tile 32x64, k-tile 32.
// Grid: (N/128, M/128, batch)
// ---------------------------------------------------------------------------
#define GLDA 36
#define GLDB 136
__global__ __launch_bounds__(256) void gemm_tf32(
    const float* __restrict__ A, const float* __restrict__ Bg,
    float* __restrict__ Cg, int M, int N, int K)
{
    __shared__ float as[128 * GLDA];
    __shared__ float bs[32 * GLDB];

    const int bz = blockIdx.z;
    const float* Bp = Bg + (size_t)bz * K * N;
    float*       Cp = Cg + (size_t)bz * M * N;

    const int tid = threadIdx.x;
    const int warp = tid >> 5, lane = tid & 31;
    const int wm = warp >> 1, wn = warp & 1;
    const int g = lane >> 2, t = lane & 3;
    const int row0 = blockIdx.y * 128;
    const int col0 = blockIdx.x * 128;

    float acc[2][8][4];
    #pragma unroll
    for (int i = 0; i < 2; i++)
        #pragma unroll
        for (int j = 0; j < 8; j++)
            #pragma unroll
            for (int e = 0; e < 4; e++) acc[i][j][e] = 0.f;

    float4 ra[4], rb[4];
    const int nk = K / 32;

    // prefetch tile 0
    #pragma unroll
    for (int i = 0; i < 4; i++) {
        int idx = tid + i * 256;
        ra[i] = *(const float4*)&A [(size_t)(row0 + (idx >> 3)) * K + (idx & 7) * 4];
        rb[i] = *(const float4*)&Bp[(size_t)(idx >> 5) * N + col0 + (idx & 31) * 4];
    }
    #pragma unroll
    for (int i = 0; i < 4; i++) {
        int idx = tid + i * 256;
        float4 wa = make_float4(f2tf_f(ra[i].x), f2tf_f(ra[i].y), f2tf_f(ra[i].z), f2tf_f(ra[i].w));
        *(float4*)&as[(idx >> 3) * GLDA + (idx & 7) * 4] = wa;
        float4 wb = make_float4(f2tf_f(rb[i].x), f2tf_f(rb[i].y), f2tf_f(rb[i].z), f2tf_f(rb[i].w));
        *(float4*)&bs[(idx >> 5) * GLDB + (idx & 31) * 4] = wb;
    }
    __syncthreads();

    for (int kt = 0; kt < nk; kt++) {
        if (kt + 1 < nk) {
            #pragma unroll
            for (int i = 0; i < 4; i++) {
                int idx = tid + i * 256;
                ra[i] = *(const float4*)&A [(size_t)(row0 + (idx >> 3)) * K + (kt + 1) * 32 + (idx & 7) * 4];
                rb[i] = *(const float4*)&Bp[(size_t)((kt + 1) * 32 + (idx >> 5)) * N + col0 + (idx & 31) * 4];
            }
        }
        #pragma unroll
        for (int ks = 0; ks < 4; ks++) {
            unsigned a[2][4];
            #pragma unroll
            for (int i = 0; i < 2; i++) {
                int r = wm * 32 + 16 * i + g;
                a[i][0] = __float_as_uint(as[r * GLDA + ks * 8 + t]);
                a[i][1] = __float_as_uint(as[(r + 8) * GLDA + ks * 8 + t]);
                a[i][2] = __float_as_uint(as[r * GLDA + ks * 8 + t + 4]);
                a[i][3] = __float_as_uint(as[(r + 8) * GLDA + ks * 8 + t + 4]);
            }
            #pragma unroll
            for (int j = 0; j < 8; j++) {
                unsigned b0 = __float_as_uint(bs[(ks * 8 + t) * GLDB + wn * 64 + 8 * j + g]);
                unsigned b1 = __float_as_uint(bs[(ks * 8 + t + 4) * GLDB + wn * 64 + 8 * j + g]);
                mma_tf32(acc[0][j], a[0][0], a[0][1], a[0][2], a[0][3], b0, b1);
                mma_tf32(acc[1][j], a[1][0], a[1][1], a[1][2], a[1][3], b0, b1);
            }
        }
        __syncthreads();
        if (kt + 1 < nk) {
            #pragma unroll
            for (int i = 0; i < 4; i++) {
                int idx = tid + i * 256;
                float4 wa = make_float4(f2tf_f(ra[i].x), f2tf_f(ra[i].y), f2tf_f(ra[i].z), f2tf_f(ra[i].w));
                *(float4*)&as[(idx >> 3) * GLDA + (idx & 7) * 4] = wa;
                float4 wb = make_float4(f2tf_f(rb[i].x), f2tf_f(rb[i].y), f2tf_f(rb[i].z), f2tf_f(rb[i].w));
                *(float4*)&bs[(idx >> 5) * GLDB + (idx & 31) * 4] = wb;
            }
            __syncthreads();
        }
    }

    #pragma unroll
    for (int i = 0; i < 2; i++) {
        int r = row0 + wm * 32 + 16 * i + g;
        #pragma unroll
        for (int j = 0; j < 8; j++) {
            int c = col0 + wn * 64 + 8 * j + 2 * t;
            *(float2*)&Cp[(size_t)r * N + c]       = make_float2(acc[i][j][0], acc[i][j][1]);
            *(float2*)&Cp[(size_t)(r + 8) * N + c] = make_float2(acc[i][j][2], acc[i][j][3]);
        }
    }
}

// ---------------------------------------------------------------------------
// Fused flash attention with tf32 MMA.
// Block = 128 threads (4 warps), handles 128 query rows of one (b,h).
// Grid: (NN/128, NH, BATCH). Dynamic smem: qs[128][68] + ks/vs[64][72].
// ---------------------------------------------------------------------------
#define ALDQ 68
#define ALDK 72
#define ATT_SMEM ((128 * ALDQ + 2 * 64 * ALDK) * 4)

__global__ __launch_bounds__(128) void attn_mma(
    const float* __restrict__ qkv, float* __restrict__ out)
{
    extern __shared__ float sm[];
    float* qs = sm;                       // [128][ALDQ]  (n, d) tf32
    float* ks = sm + 128 * ALDQ;          // [64][ALDK]   (d, m) tf32
    float* vs = ks + 64 * ALDK;           // [64][ALDK]   (d, m) tf32

    const int b = blockIdx.z, h = blockIdx.y;
    const int n0 = blockIdx.x * 128;
    const int tid = threadIdx.x, warp = tid >> 5, lane = tid & 31;
    const int g = lane >> 2, t = lane & 3;
    const int rowbase = warp * 32;

    const float* q = qkv + (((size_t)b * 3 + 0) * NH + h) * HD * NN;
    const float* k = qkv + (((size_t)b * 3 + 1) * NH + h) * HD * NN;
    const float* v = qkv + (((size_t)b * 3 + 2) * NH + h) * HD * NN;

    // Load Q tile (transposed to (n,d)), scale by hd^-0.5 = 0.125, cvt tf32
    #pragma unroll
    for (int i = 0; i < 16; i++) {
        int idx = tid + i * 128;
        int d = idx >> 5, n4 = (idx & 31) * 4;
        float4 val = *(const float4*)&q[(size_t)d * NN + n0 + n4];
        qs[(n4 + 0) * ALDQ + d] = f2tf_f(0.125f * val.x);
        qs[(n4 + 1) * ALDQ + d] = f2tf_f(0.125f * val.y);
        qs[(n4 + 2) * ALDQ + d] = f2tf_f(0.125f * val.z);
        qs[(n4 + 3) * ALDQ + d] = f2tf_f(0.125f * val.w);
    }

    float o[2][8][4];
    float Mx[2][2], L[2][2];
    #pragma unroll
    for (int i = 0; i < 2; i++) {
        #pragma unroll
        for (int j = 0; j < 8; j++)
            #pragma unroll
            for (int e = 0; e < 4; e++) o[i][j][e] = 0.f;
        Mx[i][0] = Mx[i][1] = -1e30f;
        L[i][0] = L[i][1] = 0.f;
    }

    const int src0 = (lane & ~3) | (t >> 1);
    const int src1 = src0 + 2;
    const bool odd = (t & 1);

    for (int mt = 0; mt < NN / 64; mt++) {
        const int m0 = mt * 64;
        __syncthreads();   // previous tile fully consumed (and Q visible on mt=0)
        #pragma unroll
        for (int i = 0; i < 8; i++) {
            int idx = tid + i * 128;
            int d = idx >> 4, m4 = (idx & 15) * 4;
            float4 kv4 = *(const float4*)&k[(size_t)d * NN + m0 + m4];
            *(float4*)&ks[d * ALDK + m4] =
                make_float4(f2tf_f(kv4.x), f2tf_f(kv4.y), f2tf_f(kv4.z), f2tf_f(kv4.w));
            float4 vv4 = *(const float4*)&v[(size_t)d * NN + m0 + m4];
            *(float4*)&vs[d * ALDK + m4] =
                make_float4(f2tf_f(vv4.x), f2tf_f(vv4.y), f2tf_f(vv4.z), f2tf_f(vv4.w));
        }
        __syncthreads();

        // ---- S = Q * K  (128x64 per block, 32x64 per warp) ----
        float s[2][8][4];
        #pragma unroll
        for (int i = 0; i < 2; i++)
            #pragma unroll
            for (int j = 0; j < 8; j++)
                #pragma unroll
                for (int e = 0; e < 4; e++) s[i][j][e] = 0.f;

        #pragma unroll
        for (int ks8 = 0; ks8 < 8; ks8++) {
            unsigned a[2][4];
            #pragma unroll
            for (int i = 0; i < 2; i++) {
                int r = rowbase + 16 * i + g;
                a[i][0] = __float_as_uint(qs[r * ALDQ + ks8 * 8 + t]);
                a[i][1] = __float_as_uint(qs[(r + 8) * ALDQ + ks8 * 8 + t]);
                a[i][2] = __float_as_uint(qs[r * ALDQ + ks8 * 8 + t + 4]);
                a[i][3] = __float_as_uint(qs[(r + 8) * ALDQ + ks8 * 8 + t + 4]);
            }
            #pragma unroll
            for (int j = 0; j < 8; j++) {
                unsigned b0 = __float_as_uint(ks[(ks8 * 8 + t) * ALDK + 8 * j + g]);
                unsigned b1 = __float_as_uint(ks[(ks8 * 8 + t + 4) * ALDK + 8 * j + g]);
                mma_tf32(s[0][j], a[0][0], a[0][1], a[0][2], a[0][3], b0, b1);
                mma_tf32(s[1][j], a[1][0], a[1][1], a[1][2], a[1][3], b0, b1);
            }
        }

        // ---- online softmax ----
        #pragma unroll
        for (int i = 0; i < 2; i++) {
            #pragma unroll
            for (int rh = 0; rh < 2; rh++) {
                float tm = -1e30f;
                #pragma unroll
                for (int j = 0; j < 8; j++)
                    tm = fmaxf(tm, fmaxf(s[i][j][2 * rh], s[i][j][2 * rh + 1]));
                tm = fmaxf(tm, __shfl_xor_sync(0xffffffffu, tm, 1));
                tm = fmaxf(tm, __shfl_xor_sync(0xffffffffu, tm, 2));
                float nM = fmaxf(Mx[i][rh], tm);
                float corr = __expf(Mx[i][rh] - nM);
                Mx[i][rh] = nM;
                float ls = 0.f;
                #pragma unroll
                for (int j = 0; j < 8; j++) {
                    float p0 = __expf(s[i][j][2 * rh] - nM);
                    float p1 = __expf(s[i][j][2 * rh + 1] - nM);
                    s[i][j][2 * rh] = p0;
                    s[i][j][2 * rh + 1] = p1;
                    ls += p0 + p1;
                }
                ls += __shfl_xor_sync(0xffffffffu, ls, 1);
                ls += __shfl_xor_sync(0xffffffffu, ls, 2);
                L[i][rh] = L[i][rh] * corr + ls;
                #pragma unroll
                for (int j = 0; j < 8; j++) {
                    o[i][j][2 * rh]     *= corr;
                    o[i][j][2 * rh + 1] *= corr;
                }
            }
        }
        // convert P to tf32 bits in place
        #pragma unroll
        for (int i = 0; i < 2; i++)
            #pragma unroll
            for (int j = 0; j < 8; j++)
                #pragma unroll
                for (int e = 0; e < 4; e++)
                    s[i][j][e] = __uint_as_float(f2tf(s[i][j][e]));

        // ---- O += P * V  (C-frag -> A-frag via shuffles) ----
        #pragma unroll
        for (int ms = 0; ms < 8; ms++) {
            unsigned a[2][4];
            #pragma unroll
            for (int i = 0; i < 2; i++) {
                float x0 = __shfl_sync(0xffffffffu, s[i][ms][0], src0);
                float x1 = __shfl_sync(0xffffffffu, s[i][ms][1], src0);
                float y0 = __shfl_sync(0xffffffffu, s[i][ms][0], src1);
                float y1 = __shfl_sync(0xffffffffu, s[i][ms][1], src1);
                float z0 = __shfl_sync(0xffffffffu, s[i][ms][2], src0);
                float z1 = __shfl_sync(0xffffffffu, s[i][ms][3], src0);
                float w0 = __shfl_sync(0xffffffffu, s[i][ms][2], src1);
                float w1 = __shfl_sync(0xffffffffu, s[i][ms][3], src1);
                a[i][0] = __float_as_uint(odd ? x1 : x0);
                a[i][1] = __float_as_uint(odd ? z1 : z0);
                a[i][2] = __float_as_uint(odd ? y1 : y0);
                a[i][3] = __float_as_uint(odd ? w1 : w0);
            }
            #pragma unroll
            for (int j = 0; j < 8; j++) {
                unsigned b0 = __float_as_uint(vs[(8 * j + g) * ALDK + ms * 8 + t]);
                unsigned b1 = __float_as_uint(vs[(8 * j + g) * ALDK + ms * 8 + t + 4]);
                mma_tf32(o[0][j], a[0][0], a[0][1], a[0][2], a[0][3], b0, b1);
                mma_tf32(o[1][j], a[1][0], a[1][1], a[1][2], a[1][3], b0, b1);
            }
        }
    }

    // ---- write O (transposed back to (d, n) layout) ----
    #pragma unroll
    for (int i = 0; i < 2; i++) {
        float inv0 = 1.f / L[i][0];
        float inv1 = 1.f / L[i][1];
        int r0 = n0 + rowbase + 16 * i + g;
        int r1 = r0 + 8;
        #pragma unroll
        for (int j = 0; j < 8; j++) {
            int d = 8 * j + 2 * t;
            size_t base = ((size_t)b * CH + h * HD + d) * NN;
            out[base + r0]      = o[i][j][0] * inv0;
            out[base + NN + r0] = o[i][j][1] * inv0;
            out[base + r1]      = o[i][j][2] * inv1;
            out[base + NN + r1] = o[i][j][3] * inv1;
        }
    }
}

// ---------------------------------------------------------------------------
// GroupNorm(affine) + residual.  One block per (b,g). 512 threads.
// ---------------------------------------------------------------------------
__global__ __launch_bounds__(512) void gn_kernel(
    const float* __restrict__ pin, const float* __restrict__ x,
    const float* __restrict__ gamma, const float* __restrict__ beta,
    float* __restrict__ out)
{
    const int b = blockIdx.x >> 3;
    const int g = blockIdx.x & 7;
    const size_t base = ((size_t)b * CH + g * CPG) * NN;
    const float4* p4 = (const float4*)(pin + base);
    const float4* x4 = (const float4*)(x + base);
    float4*       o4 = (float4*)(out + base);

    const int tid = threadIdx.x;
    float sum = 0.f, ss = 0.f;
    for (int i = tid; i < 16384; i += 512) {
        float4 p = p4[i];
        sum += p.x + p.y + p.z + p.w;
        ss  += p.x * p.x + p.y * p.y + p.z * p.z + p.w * p.w;
    }
    #pragma unroll
    for (int off = 16; off; off >>= 1) {
        sum += __shfl_xor_sync(0xffffffffu, sum, off);
        ss  += __shfl_xor_sync(0xffffffffu, ss, off);
    }
    __shared__ float reds[16], redq[16], stats[2];
    const int warp = tid >> 5, lane = tid & 31;
    if (lane == 0) { reds[warp] = sum; redq[warp] = ss; }
    __syncthreads();
    if (tid == 0) {
        float s = 0.f, q = 0.f;
        #pragma unroll
        for (int w = 0; w < 16; w++) { s += reds[w]; q += redq[w]; }
        const float invn = 1.f / 65536.f;
        float mean = s * invn;
        float var  = q * invn - mean * mean;
        stats[0] = mean;
        stats[1] = rsqrtf(var + GN_EPS);
    }
    __syncthreads();
    const float mean = stats[0], inv = stats[1];

    for (int i = tid; i < 16384; i += 512) {
        int c = g * CPG + (i >> 8);
        float ga = gamma[c], be = beta[c];
        float4 p = p4[i];
        float4 xv = x4[i];
        float4 r;
        r.x = (p.x - mean) * inv * ga + be + xv.x;
        r.y = (p.y - mean) * inv * ga + be + xv.y;
        r.z = (p.z - mean) * inv * ga + be + xv.z;
        r.w = (p.w - mean) * inv * ga + be + xv.w;
        o4[i] = r;
    }
}

// ---------------------------------------------------------------------------
extern "C" void kernel_launch(void* const* d_in, const int* in_sizes, int n_in,
                              void* d_out, int out_size)
{
    const float* x      = (const float*)d_in[0];
    const float* w_qkv  = (const float*)d_in[1];
    const float* w_proj = (const float*)d_in[2];
    const float* gamma  = (const float*)d_in[3];
    const float* beta   = (const float*)d_in[4];
    float* out = (float*)d_out;

    float* qkv;  cudaGetSymbolAddress((void**)&qkv,  g_qkv);
    float* att;  cudaGetSymbolAddress((void**)&att,  g_att);
    float* proj; cudaGetSymbolAddress((void**)&proj, g_proj);

    static bool attr_set = false;
    if (!attr_set) {
        cudaFuncSetAttribute(attn_mma,
            cudaFuncAttributeMaxDynamicSharedMemorySize, ATT_SMEM);
        attr_set = true;
    }

    // 1) QKV projection: (1536x512) * (512x1024) per batch
    gemm_tf32<<<dim3(NN / 128, (3 * CH) / 128, BATCH), 256>>>(
        w_qkv, x, qkv, 3 * CH, NN, CH);

    // 2) Fused flash attention per (b,h)
    attn_mma<<<dim3(NN / 128, NH, BATCH), 128, ATT_SMEM>>>(qkv, att);

    // 3) Output projection: (512x512) * (512x1024) per batch
    gemm_tf32<<<dim3(NN / 128, CH / 128, BATCH), 256>>>(
        w_proj, att, proj, CH, NN, CH);

    // 4) GroupNorm + affine + residual
    gn_kernel<<<BATCH * GRP, 512>>>(proj, x, gamma, beta, out);
}

// round 5
// speedup vs baseline: 7.6656x; 1.5793x over previous
#include <cuda_runtime.h>
#include <cuda_fp16.h>
#include <math.h>
#include <stdint.h>

#define BATCH 8
#define CH    512
#define NN    1024
#define NH    8
#define HD    64
#define GRP   8
#define CPG   64
#define GN_EPS 1e-5f

__device__ float g_qkv[(size_t)BATCH * 3 * CH * NN];
__device__ float g_att[(size_t)BATCH * CH * NN];
__device__ float g_proj[(size_t)BATCH * CH * NN];

// ---------------------------------------------------------------------------
// helpers
// ---------------------------------------------------------------------------
__device__ __forceinline__ uint32_t smem_u32(const void* p) {
    uint32_t a;
    asm("{ .reg .u64 t; cvta.to.shared.u64 t, %1; cvt.u32.u64 %0, t; }" : "=r"(a) : "l"(p));
    return a;
}
__device__ __forceinline__ uint32_t pk(float x, float y) {
    __half2 h = __floats2half2_rn(x, y);
    return *(uint32_t*)&h;
}
__device__ __forceinline__ void mma16816(float* c, const uint32_t* a,
                                         uint32_t b0, uint32_t b1) {
    asm volatile(
        "mma.sync.aligned.m16n8k16.row.col.f32.f16.f16.f32 "
        "{%0,%1,%2,%3},{%4,%5,%6,%7},{%8,%9},{%0,%1,%2,%3};"
        : "+f"(c[0]), "+f"(c[1]), "+f"(c[2]), "+f"(c[3])
        : "r"(a[0]), "r"(a[1]), "r"(a[2]), "r"(a[3]), "r"(b0), "r"(b1));
}
__device__ __forceinline__ void ldsm4(uint32_t* r, uint32_t addr) {
    asm volatile("ldmatrix.sync.aligned.m8n8.x4.shared.b16 {%0,%1,%2,%3}, [%4];"
        : "=r"(r[0]), "=r"(r[1]), "=r"(r[2]), "=r"(r[3]) : "r"(addr));
}
__device__ __forceinline__ void ldsm4t(uint32_t* r, uint32_t addr) {
    asm volatile("ldmatrix.sync.aligned.m8n8.x4.trans.shared.b16 {%0,%1,%2,%3}, [%4];"
        : "=r"(r[0]), "=r"(r[1]), "=r"(r[2]), "=r"(r[3]) : "r"(addr));
}

// ---------------------------------------------------------------------------
// fp16 MMA GEMM: C[bz] (MxN) = A (MxK, shared) * B[bz] (KxN), row-major fp32.
// Block 128x128, 8 warps (4x2), warp tile 32x64, k-tile 32.
// ---------------------------------------------------------------------------
#define LDA 40    // halves per A row (80B, 16B-aligned stride)
#define LDB 136   // halves per B row (272B)
__global__ __launch_bounds__(256) void gemm_h(
    const float* __restrict__ A, const float* __restrict__ Bg,
    float* __restrict__ Cg, int M, int N, int K)
{
    __shared__ __half as[128 * LDA];
    __shared__ __half bs[32 * LDB];

    const int bz = blockIdx.z;
    const float* Bp = Bg + (size_t)bz * K * N;
    float*       Cp = Cg + (size_t)bz * M * N;

    const int tid = threadIdx.x;
    const int warp = tid >> 5, lane = tid & 31;
    const int wm = warp >> 1, wn = warp & 1;
    const int g = lane >> 2, t = lane & 3;
    const int row0 = blockIdx.y * 128;
    const int col0 = blockIdx.x * 128;

    const uint32_t ab = smem_u32(as);
    const uint32_t bb = smem_u32(bs);
    // ldmatrix lane address bases (byte offsets)
    const uint32_t aAddr = ab + (((wm * 32 + (lane & 15)) * LDA) + 8 * (lane >> 4)) * 2;
    const uint32_t bAddr = bb + ((((lane & 7) + 8 * ((lane >> 3) & 1)) * LDB)
                                 + wn * 64 + 8 * (lane >> 4)) * 2;

    float acc[2][8][4];
    #pragma unroll
    for (int i = 0; i < 2; i++)
        #pragma unroll
        for (int j = 0; j < 8; j++)
            #pragma unroll
            for (int e = 0; e < 4; e++) acc[i][j][e] = 0.f;

    float4 ra[2], rb[2];
    const int nk = K / 32;
    const int arow = tid >> 3, ac4 = (tid & 7) * 4;       // A: 128x32
    const int brow = tid >> 5, bn4 = (tid & 31) * 4;      // B: 32x128

    // prefetch tile 0
    ra[0] = *(const float4*)&A [(size_t)(row0 + arow) * K + ac4];
    ra[1] = *(const float4*)&A [(size_t)(row0 + arow + 32) * K + ac4];
    rb[0] = *(const float4*)&Bp[(size_t)brow * N + col0 + bn4];
    rb[1] = *(const float4*)&Bp[(size_t)(brow + 8) * N + col0 + bn4];
    // wait: A tile is 128 rows; 256 threads x (idx>>3) covers 32 rows per 256.
    // redo with 4 chunks below.

    float4 pa[4], pb[4];
    #pragma unroll
    for (int i = 0; i < 4; i++) {
        int idx = tid + i * 256;
        pa[i] = *(const float4*)&A [(size_t)(row0 + (idx >> 3)) * K + (idx & 7) * 4];
        pb[i] = *(const float4*)&Bp[(size_t)(idx >> 5) * N + col0 + (idx & 31) * 4];
    }
    #pragma unroll
    for (int i = 0; i < 4; i++) {
        int idx = tid + i * 256;
        *(uint2*)&as[(idx >> 3) * LDA + (idx & 7) * 4] =
            make_uint2(pk(pa[i].x, pa[i].y), pk(pa[i].z, pa[i].w));
        *(uint2*)&bs[(idx >> 5) * LDB + (idx & 31) * 4] =
            make_uint2(pk(pb[i].x, pb[i].y), pk(pb[i].z, pb[i].w));
    }
    __syncthreads();

    for (int kt = 0; kt < nk; kt++) {
        if (kt + 1 < nk) {
            #pragma unroll
            for (int i = 0; i < 4; i++) {
                int idx = tid + i * 256;
                pa[i] = *(const float4*)&A [(size_t)(row0 + (idx >> 3)) * K + (kt + 1) * 32 + (idx & 7) * 4];
                pb[i] = *(const float4*)&Bp[(size_t)((kt + 1) * 32 + (idx >> 5)) * N + col0 + (idx & 31) * 4];
            }
        }
        #pragma unroll
        for (int ks = 0; ks < 2; ks++) {
            uint32_t a[2][4];
            ldsm4(a[0], aAddr + ks * 32);
            ldsm4(a[1], aAddr + ks * 32 + 16 * LDA * 2);
            #pragma unroll
            for (int jj = 0; jj < 4; jj++) {
                uint32_t b[4];
                ldsm4t(b, bAddr + ks * 16 * LDB * 2 + jj * 32);
                mma16816(acc[0][2 * jj],     a[0], b[0], b[1]);
                mma16816(acc[0][2 * jj + 1], a[0], b[2], b[3]);
                mma16816(acc[1][2 * jj],     a[1], b[0], b[1]);
                mma16816(acc[1][2 * jj + 1], a[1], b[2], b[3]);
            }
        }
        __syncthreads();
        if (kt + 1 < nk) {
            #pragma unroll
            for (int i = 0; i < 4; i++) {
                int idx = tid + i * 256;
                *(uint2*)&as[(idx >> 3) * LDA + (idx & 7) * 4] =
                    make_uint2(pk(pa[i].x, pa[i].y), pk(pa[i].z, pa[i].w));
                *(uint2*)&bs[(idx >> 5) * LDB + (idx & 31) * 4] =
                    make_uint2(pk(pb[i].x, pb[i].y), pk(pb[i].z, pb[i].w));
            }
            __syncthreads();
        }
    }

    #pragma unroll
    for (int i = 0; i < 2; i++) {
        int r = row0 + wm * 32 + 16 * i + g;
        #pragma unroll
        for (int j = 0; j < 8; j++) {
            int c = col0 + wn * 64 + 8 * j + 2 * t;
            *(float2*)&Cp[(size_t)r * N + c]       = make_float2(acc[i][j][0], acc[i][j][1]);
            *(float2*)&Cp[(size_t)(r + 8) * N + c] = make_float2(acc[i][j][2], acc[i][j][3]);
        }
    }
}

// ---------------------------------------------------------------------------
// Fused flash attention, fp16 mma.sync m16n8k16.
// Block = 128 threads (4 warps) = 128 query rows of one (b,h).
// qs: [128 n][72 d] halves; ks/vs: [64 d][72 m] halves (natural layout).
// ---------------------------------------------------------------------------
#define LDQ 72
#define LDK 72
#define ATT_SMEM ((128 * LDQ + 2 * 64 * LDK) * 2)

__global__ __launch_bounds__(128) void attn_h(
    const float* __restrict__ qkv, float* __restrict__ out)
{
    extern __shared__ __half smh[];
    __half* qs = smh;                 // [128][LDQ]
    __half* ks = smh + 128 * LDQ;     // [64][LDK]
    __half* vs = ks + 64 * LDK;       // [64][LDK]

    const int b = blockIdx.z, h = blockIdx.y;
    const int n0 = blockIdx.x * 128;
    const int tid = threadIdx.x, warp = tid >> 5, lane = tid & 31;
    const int g = lane >> 2, t = lane & 3;
    const int rowbase = warp * 32;

    const float* q = qkv + (((size_t)b * 3 + 0) * NH + h) * HD * NN;
    const float* k = qkv + (((size_t)b * 3 + 1) * NH + h) * HD * NN;
    const float* v = qkv + (((size_t)b * 3 + 2) * NH + h) * HD * NN;

    const uint32_t qb = smem_u32(qs);
    const uint32_t kb = smem_u32(ks);
    const uint32_t vb = smem_u32(vs);
    const uint32_t qAddr = qb + (((rowbase + (lane & 15)) * LDQ) + 8 * (lane >> 4)) * 2;
    const uint32_t kAddr = kb + ((((lane & 7) + 8 * ((lane >> 3) & 1)) * LDK)
                                 + 8 * (lane >> 4)) * 2;
    const uint32_t vAddr = vb + ((((lane & 7) + 8 * (lane >> 4)) * LDK)
                                 + 8 * ((lane >> 3) & 1)) * 2;

    // Q fill: transpose to [n][d], scale, convert. Thread tid owns n=tid.
    {
        const int n = tid;
        #pragma unroll
        for (int it = 0; it < 16; it++) {
            int d0 = it * 4;
            float q0 = q[(size_t)(d0 + 0) * NN + n0 + n];
            float q1 = q[(size_t)(d0 + 1) * NN + n0 + n];
            float q2 = q[(size_t)(d0 + 2) * NN + n0 + n];
            float q3 = q[(size_t)(d0 + 3) * NN + n0 + n];
            *(uint2*)&qs[n * LDQ + d0] = make_uint2(
                pk(0.125f * q0, 0.125f * q1), pk(0.125f * q2, 0.125f * q3));
        }
    }

    float o[2][8][4];
    float Mx[2][2], L[2][2];
    #pragma unroll
    for (int i = 0; i < 2; i++) {
        #pragma unroll
        for (int j = 0; j < 8; j++)
            #pragma unroll
            for (int e = 0; e < 4; e++) o[i][j][e] = 0.f;
        Mx[i][0] = Mx[i][1] = -1e30f;
        L[i][0] = L[i][1] = 0.f;
    }

    for (int mt = 0; mt < NN / 64; mt++) {
        const int m0 = mt * 64;
        __syncthreads();
        // K/V fill: natural [d][m] layout, fp32->fp16
        #pragma unroll
        for (int i = 0; i < 8; i++) {
            int idx = tid + i * 128;
            int d = idx >> 4, m4 = (idx & 15) * 4;
            float4 kv4 = *(const float4*)&k[(size_t)d * NN + m0 + m4];
            *(uint2*)&ks[d * LDK + m4] = make_uint2(pk(kv4.x, kv4.y), pk(kv4.z, kv4.w));
            float4 vv4 = *(const float4*)&v[(size_t)d * NN + m0 + m4];
            *(uint2*)&vs[d * LDK + m4] = make_uint2(pk(vv4.x, vv4.y), pk(vv4.z, vv4.w));
        }
        __syncthreads();

        // ---- S = Q * K^T : per warp 32(n) x 64(m), k = d = 64 ----
        float s[2][8][4];
        #pragma unroll
        for (int i = 0; i < 2; i++)
            #pragma unroll
            for (int j = 0; j < 8; j++)
                #pragma unroll
                for (int e = 0; e < 4; e++) s[i][j][e] = 0.f;

        #pragma unroll
        for (int ks16 = 0; ks16 < 4; ks16++) {
            uint32_t a[2][4];
            ldsm4(a[0], qAddr + ks16 * 32);
            ldsm4(a[1], qAddr + ks16 * 32 + 16 * LDQ * 2);
            #pragma unroll
            for (int jj = 0; jj < 4; jj++) {
                uint32_t bf[4];
                ldsm4t(bf, kAddr + ks16 * 16 * LDK * 2 + jj * 32);
                mma16816(s[0][2 * jj],     a[0], bf[0], bf[1]);
                mma16816(s[0][2 * jj + 1], a[0], bf[2], bf[3]);
                mma16816(s[1][2 * jj],     a[1], bf[0], bf[1]);
                mma16816(s[1][2 * jj + 1], a[1], bf[2], bf[3]);
            }
        }

        // ---- online softmax ----
        #pragma unroll
        for (int i = 0; i < 2; i++) {
            #pragma unroll
            for (int rh = 0; rh < 2; rh++) {
                float tm = -1e30f;
                #pragma unroll
                for (int j = 0; j < 8; j++)
                    tm = fmaxf(tm, fmaxf(s[i][j][2 * rh], s[i][j][2 * rh + 1]));
                tm = fmaxf(tm, __shfl_xor_sync(0xffffffffu, tm, 1));
                tm = fmaxf(tm, __shfl_xor_sync(0xffffffffu, tm, 2));
                float nM = fmaxf(Mx[i][rh], tm);
                float corr = __expf(Mx[i][rh] - nM);
                Mx[i][rh] = nM;
                float ls = 0.f;
                #pragma unroll
                for (int j = 0; j < 8; j++) {
                    float p0 = __expf(s[i][j][2 * rh] - nM);
                    float p1 = __expf(s[i][j][2 * rh + 1] - nM);
                    s[i][j][2 * rh] = p0;
                    s[i][j][2 * rh + 1] = p1;
                    ls += p0 + p1;
                }
                ls += __shfl_xor_sync(0xffffffffu, ls, 1);
                ls += __shfl_xor_sync(0xffffffffu, ls, 2);
                L[i][rh] = L[i][rh] * corr + ls;
                #pragma unroll
                for (int j = 0; j < 8; j++) {
                    o[i][j][2 * rh]     *= corr;
                    o[i][j][2 * rh + 1] *= corr;
                }
            }
        }

        // ---- O += P * V^T : A-frag = packed C-frags, B via ldmatrix ----
        #pragma unroll
        for (int ms2 = 0; ms2 < 4; ms2++) {
            uint32_t aP[2][4];
            #pragma unroll
            for (int i = 0; i < 2; i++) {
                aP[i][0] = pk(s[i][2 * ms2][0],     s[i][2 * ms2][1]);
                aP[i][1] = pk(s[i][2 * ms2][2],     s[i][2 * ms2][3]);
                aP[i][2] = pk(s[i][2 * ms2 + 1][0], s[i][2 * ms2 + 1][1]);
                aP[i][3] = pk(s[i][2 * ms2 + 1][2], s[i][2 * ms2 + 1][3]);
            }
            #pragma unroll
            for (int jj = 0; jj < 4; jj++) {
                uint32_t bf[4];
                ldsm4(bf, vAddr + jj * 16 * LDK * 2 + ms2 * 32);
                mma16816(o[0][2 * jj],     aP[0], bf[0], bf[1]);
                mma16816(o[0][2 * jj + 1], aP[0], bf[2], bf[3]);
                mma16816(o[1][2 * jj],     aP[1], bf[0], bf[1]);
                mma16816(o[1][2 * jj + 1], aP[1], bf[2], bf[3]);
            }
        }
    }

    // ---- write O (to [d][n] layout) ----
    #pragma unroll
    for (int i = 0; i < 2; i++) {
        float inv0 = 1.f / L[i][0];
        float inv1 = 1.f / L[i][1];
        int r0 = n0 + rowbase + 16 * i + g;
        int r1 = r0 + 8;
        #pragma unroll
        for (int j = 0; j < 8; j++) {
            int d = 8 * j + 2 * t;
            size_t base = ((size_t)b * CH + h * HD + d) * NN;
            out[base + r0]      = o[i][j][0] * inv0;
            out[base + NN + r0] = o[i][j][1] * inv0;
            out[base + r1]      = o[i][j][2] * inv1;
            out[base + NN + r1] = o[i][j][3] * inv1;
        }
    }
}

// ---------------------------------------------------------------------------
// GroupNorm + residual (unchanged)
// ---------------------------------------------------------------------------
__global__ __launch_bounds__(512) void gn_kernel(
    const float* __restrict__ pin, const float* __restrict__ x,
    const float* __restrict__ gamma, const float* __restrict__ beta,
    float* __restrict__ out)
{
    const int b = blockIdx.x >> 3;
    const int g = blockIdx.x & 7;
    const size_t base = ((size_t)b * CH + g * CPG) * NN;
    const float4* p4 = (const float4*)(pin + base);
    const float4* x4 = (const float4*)(x + base);
    float4*       o4 = (float4*)(out + base);

    const int tid = threadIdx.x;
    float sum = 0.f, ss = 0.f;
    for (int i = tid; i < 16384; i += 512) {
        float4 p = p4[i];
        sum += p.x + p.y + p.z + p.w;
        ss  += p.x * p.x + p.y * p.y + p.z * p.z + p.w * p.w;
    }
    #pragma unroll
    for (int off = 16; off; off >>= 1) {
        sum += __shfl_xor_sync(0xffffffffu, sum, off);
        ss  += __shfl_xor_sync(0xffffffffu, ss, off);
    }
    __shared__ float reds[16], redq[16], stats[2];
    const int warp = tid >> 5, lane = tid & 31;
    if (lane == 0) { reds[warp] = sum; redq[warp] = ss; }
    __syncthreads();
    if (tid == 0) {
        float s = 0.f, q = 0.f;
        #pragma unroll
        for (int w = 0; w < 16; w++) { s += reds[w]; q += redq[w]; }
        const float invn = 1.f / 65536.f;
        float mean = s * invn;
        float var  = q * invn - mean * mean;
        stats[0] = mean;
        stats[1] = rsqrtf(var + GN_EPS);
    }
    __syncthreads();
    const float mean = stats[0], inv = stats[1];

    for (int i = tid; i < 16384; i += 512) {
        int c = g * CPG + (i >> 8);
        float ga = gamma[c], be = beta[c];
        float4 p = p4[i];
        float4 xv = x4[i];
        float4 r;
        r.x = (p.x - mean) * inv * ga + be + xv.x;
        r.y = (p.y - mean) * inv * ga + be + xv.y;
        r.z = (p.z - mean) * inv * ga + be + xv.z;
        r.w = (p.w - mean) * inv * ga + be + xv.w;
        o4[i] = r;
    }
}

// ---------------------------------------------------------------------------
extern "C" void kernel_launch(void* const* d_in, const int* in_sizes, int n_in,
                              void* d_out, int out_size)
{
    const float* x      = (const float*)d_in[0];
    const float* w_qkv  = (const float*)d_in[1];
    const float* w_proj = (const float*)d_in[2];
    const float* gamma  = (const float*)d_in[3];
    const float* beta   = (const float*)d_in[4];
    float* out = (float*)d_out;

    float* qkv;  cudaGetSymbolAddress((void**)&qkv,  g_qkv);
    float* att;  cudaGetSymbolAddress((void**)&att,  g_att);
    float* proj; cudaGetSymbolAddress((void**)&proj, g_proj);

    static bool attr_set = false;
    if (!attr_set) {
        cudaFuncSetAttribute(attn_h,
            cudaFuncAttributeMaxDynamicSharedMemorySize, ATT_SMEM);
        attr_set = true;
    }

    // 1) QKV projection: (1536x512) * (512x1024) per batch
    gemm_h<<<dim3(NN / 128, (3 * CH) / 128, BATCH), 256>>>(
        w_qkv, x, qkv, 3 * CH, NN, CH);

    // 2) Fused flash attention per (b,h)
    attn_h<<<dim3(NN / 128, NH, BATCH), 128, ATT_SMEM>>>(qkv, att);

    // 3) Output projection: (512x512) * (512x1024) per batch
    gemm_h<<<dim3(NN / 128, CH / 128, BATCH), 256>>>(
        w_proj, att, proj, CH, NN, CH);

    // 4) GroupNorm + affine + residual
    gn_kernel<<<BATCH * GRP, 512>>>(proj, x, gamma, beta, out);
}

// round 6
// speedup vs baseline: 8.5998x; 1.1219x over previous
#include <cuda_runtime.h>
#include <cuda_fp16.h>
#include <math.h>
#include <stdint.h>

#define BATCH 8
#define CH    512
#define NN    1024
#define NH    8
#define HD    64
#define CPG   64
#define GN_EPS 1e-5f

__device__ __half g_qkvh[(size_t)BATCH * 3 * CH * NN];   // fp16 [B,1536,1024]
__device__ __half g_atth[(size_t)BATCH * CH * NN];       // fp16 [B,512,1024]
__device__ float  g_proj[(size_t)BATCH * CH * NN];
__device__ float  g_part[64 * 8 * 2];

// ---------------------------------------------------------------------------
// helpers
// ---------------------------------------------------------------------------
__device__ __forceinline__ uint32_t smem_u32(const void* p) {
    uint32_t a;
    asm("{ .reg .u64 t; cvta.to.shared.u64 t, %1; cvt.u32.u64 %0, t; }" : "=r"(a) : "l"(p));
    return a;
}
__device__ __forceinline__ uint32_t pk(float x, float y) {
    __half2 h = __floats2half2_rn(x, y);
    return *(uint32_t*)&h;
}
__device__ __forceinline__ void mma16816(float* c, const uint32_t* a,
                                         uint32_t b0, uint32_t b1) {
    asm volatile(
        "mma.sync.aligned.m16n8k16.row.col.f32.f16.f16.f32 "
        "{%0,%1,%2,%3},{%4,%5,%6,%7},{%8,%9},{%0,%1,%2,%3};"
        : "+f"(c[0]), "+f"(c[1]), "+f"(c[2]), "+f"(c[3])
        : "r"(a[0]), "r"(a[1]), "r"(a[2]), "r"(a[3]), "r"(b0), "r"(b1));
}
__device__ __forceinline__ void ldsm4(uint32_t* r, uint32_t addr) {
    asm volatile("ldmatrix.sync.aligned.m8n8.x4.shared.b16 {%0,%1,%2,%3}, [%4];"
        : "=r"(r[0]), "=r"(r[1]), "=r"(r[2]), "=r"(r[3]) : "r"(addr));
}
__device__ __forceinline__ void ldsm4t(uint32_t* r, uint32_t addr) {
    asm volatile("ldmatrix.sync.aligned.m8n8.x4.trans.shared.b16 {%0,%1,%2,%3}, [%4];"
        : "=r"(r[0]), "=r"(r[1]), "=r"(r[2]), "=r"(r[3]) : "r"(addr));
}
__device__ __forceinline__ void cp_async16(uint32_t dst, const void* src) {
    asm volatile("cp.async.ca.shared.global [%0], [%1], 16;" :: "r"(dst), "l"(src));
}
#define CP_COMMIT() asm volatile("cp.async.commit_group;" ::: "memory")
#define CP_WAIT(n)  asm volatile("cp.async.wait_group %0;" :: "n"(n) : "memory")

// B-tile chunk loaders (4 elements -> 2 packed half2)
__device__ __forceinline__ uint2 ldcvt(const float* p) {
    float4 v = *(const float4*)p;
    return make_uint2(pk(v.x, v.y), pk(v.z, v.w));
}
__device__ __forceinline__ uint2 ldcvt(const __half* p) {
    return *(const uint2*)p;
}

// ---------------------------------------------------------------------------
// fp16 MMA GEMM: C[bz] (MxN) = A (MxK fp32, shared) * B[bz] (KxN).
// Block 128x128, 8 warps, warp tile 32x64, k-tile 32.
// SCALEQ: scale output rows < 512 by 0.125 (folds attention qk-scale).
// ---------------------------------------------------------------------------
#define LDA 40
#define LDB 136
template<typename TB, typename TC, bool SCALEQ>
__global__ __launch_bounds__(256) void gemm_h(
    const float* __restrict__ A, const TB* __restrict__ Bg,
    TC* __restrict__ Cg, int M, int N, int K)
{
    __shared__ __half as[128 * LDA];
    __shared__ __half bs[32 * LDB];

    const int bz = blockIdx.z;
    const TB* Bp = Bg + (size_t)bz * K * N;
    TC*       Cp = Cg + (size_t)bz * M * N;

    const int tid = threadIdx.x;
    const int warp = tid >> 5, lane = tid & 31;
    const int wm = warp >> 1, wn = warp & 1;
    const int g = lane >> 2, t = lane & 3;
    const int row0 = blockIdx.y * 128;
    const int col0 = blockIdx.x * 128;

    const uint32_t ab = smem_u32(as);
    const uint32_t bb = smem_u32(bs);
    const uint32_t aAddr = ab + (((wm * 32 + (lane & 15)) * LDA) + 8 * (lane >> 4)) * 2;
    const uint32_t bAddr = bb + ((((lane & 7) + 8 * ((lane >> 3) & 1)) * LDB)
                                 + wn * 64 + 8 * (lane >> 4)) * 2;

    float acc[2][8][4];
    #pragma unroll
    for (int i = 0; i < 2; i++)
        #pragma unroll
        for (int j = 0; j < 8; j++)
            #pragma unroll
            for (int e = 0; e < 4; e++) acc[i][j][e] = 0.f;

    const int nk = K / 32;
    float4 pa[4];
    uint2  pb[4];

    #pragma unroll
    for (int i = 0; i < 4; i++) {
        int idx = tid + i * 256;
        pa[i] = *(const float4*)&A[(size_t)(row0 + (idx >> 3)) * K + (idx & 7) * 4];
        pb[i] = ldcvt(&Bp[(size_t)(idx >> 5) * N + col0 + (idx & 31) * 4]);
    }
    #pragma unroll
    for (int i = 0; i < 4; i++) {
        int idx = tid + i * 256;
        *(uint2*)&as[(idx >> 3) * LDA + (idx & 7) * 4] =
            make_uint2(pk(pa[i].x, pa[i].y), pk(pa[i].z, pa[i].w));
        *(uint2*)&bs[(idx >> 5) * LDB + (idx & 31) * 4] = pb[i];
    }
    __syncthreads();

    for (int kt = 0; kt < nk; kt++) {
        if (kt + 1 < nk) {
            #pragma unroll
            for (int i = 0; i < 4; i++) {
                int idx = tid + i * 256;
                pa[i] = *(const float4*)&A[(size_t)(row0 + (idx >> 3)) * K + (kt + 1) * 32 + (idx & 7) * 4];
                pb[i] = ldcvt(&Bp[(size_t)((kt + 1) * 32 + (idx >> 5)) * N + col0 + (idx & 31) * 4]);
            }
        }
        #pragma unroll
        for (int ks = 0; ks < 2; ks++) {
            uint32_t a[2][4];
            ldsm4(a[0], aAddr + ks * 32);
            ldsm4(a[1], aAddr + ks * 32 + 16 * LDA * 2);
            #pragma unroll
            for (int jj = 0; jj < 4; jj++) {
                uint32_t b[4];
                ldsm4t(b, bAddr + ks * 16 * LDB * 2 + jj * 32);
                mma16816(acc[0][2 * jj],     a[0], b[0], b[1]);
                mma16816(acc[0][2 * jj + 1], a[0], b[2], b[3]);
                mma16816(acc[1][2 * jj],     a[1], b[0], b[1]);
                mma16816(acc[1][2 * jj + 1], a[1], b[2], b[3]);
            }
        }
        __syncthreads();
        if (kt + 1 < nk) {
            #pragma unroll
            for (int i = 0; i < 4; i++) {
                int idx = tid + i * 256;
                *(uint2*)&as[(idx >> 3) * LDA + (idx & 7) * 4] =
                    make_uint2(pk(pa[i].x, pa[i].y), pk(pa[i].z, pa[i].w));
                *(uint2*)&bs[(idx >> 5) * LDB + (idx & 31) * 4] = pb[i];
            }
            __syncthreads();
        }
    }

    const float cs = (SCALEQ && row0 < 512) ? 0.125f : 1.f;
    #pragma unroll
    for (int i = 0; i < 2; i++) {
        int r = row0 + wm * 32 + 16 * i + g;
        #pragma unroll
        for (int j = 0; j < 8; j++) {
            int c = col0 + wn * 64 + 8 * j + 2 * t;
            if constexpr (sizeof(TC) == 2) {
                *(uint32_t*)&Cp[(size_t)r * N + c] =
                    pk(acc[i][j][0] * cs, acc[i][j][1] * cs);
                *(uint32_t*)&Cp[(size_t)(r + 8) * N + c] =
                    pk(acc[i][j][2] * cs, acc[i][j][3] * cs);
            } else {
                *(float2*)&Cp[(size_t)r * N + c] =
                    make_float2(acc[i][j][0] * cs, acc[i][j][1] * cs);
                *(float2*)&Cp[(size_t)(r + 8) * N + c] =
                    make_float2(acc[i][j][2] * cs, acc[i][j][3] * cs);
            }
        }
    }
}

// ---------------------------------------------------------------------------
// Fused flash attention, fp16 in/out, cp.async double-buffered K/V.
// qs: [64 d][136 n] (natural, A via ldmatrix.trans); ks/vs: 2x [64 d][72 m].
// ---------------------------------------------------------------------------
#define LDQ 136
#define LDK 72
#define LDO 72
#define ATT_SMEM ((64 * LDQ + 4 * 64 * LDK) * 2)

__global__ __launch_bounds__(128) void attn_h(
    const __half* __restrict__ qkv, __half* __restrict__ outh)
{
    extern __shared__ __half smh[];
    __half* qs = smh;                       // [64][LDQ]
    __half* kv = smh + 64 * LDQ;            // 2 stages x (ks | vs), each [64][LDK]

    const int b = blockIdx.z, h = blockIdx.y;
    const int n0 = blockIdx.x * 128;
    const int tid = threadIdx.x, warp = tid >> 5, lane = tid & 31;
    const int g = lane >> 2, t = lane & 3;
    const int rowbase = warp * 32;

    const __half* q = qkv + (((size_t)b * 3 + 0) * NH + h) * HD * NN;
    const __half* k = qkv + (((size_t)b * 3 + 1) * NH + h) * HD * NN;
    const __half* v = qkv + (((size_t)b * 3 + 2) * NH + h) * HD * NN;

    const uint32_t qb  = smem_u32(qs);
    const uint32_t kvb = smem_u32(kv);
    // lane terms for ldmatrix
    const uint32_t qLane = ((((lane & 7) + 8 * (lane >> 4)) * LDQ)
                            + rowbase + 8 * ((lane >> 3) & 1)) * 2;
    const uint32_t kLane = ((((lane & 7) + 8 * ((lane >> 3) & 1)) * LDK)
                            + 8 * (lane >> 4)) * 2;
    const uint32_t vLane = ((((lane & 7) + 8 * (lane >> 4)) * LDK)
                            + 8 * ((lane >> 3) & 1)) * 2;

    auto issueKV = [&](int mt, int st) {
        const int m0 = mt * 64;
        const uint32_t kd = kvb + st * (2 * 64 * LDK) * 2;
        const uint32_t vd = kd + (64 * LDK) * 2;
        #pragma unroll
        for (int i = 0; i < 4; i++) {
            int idx = tid + i * 128;
            int d = idx >> 3, ch = idx & 7;
            cp_async16(kd + (d * LDK + ch * 8) * 2, k + (size_t)d * NN + m0 + ch * 8);
            cp_async16(vd + (d * LDK + ch * 8) * 2, v + (size_t)d * NN + m0 + ch * 8);
        }
    };

    // Q (16 chunks/row x 64 rows) + stage 0 in first group
    #pragma unroll
    for (int i = 0; i < 8; i++) {
        int idx = tid + i * 128;
        int d = idx >> 4, ch = idx & 15;
        cp_async16(qb + (d * LDQ + ch * 8) * 2, q + (size_t)d * NN + n0 + ch * 8);
    }
    issueKV(0, 0);
    CP_COMMIT();

    float o[2][8][4];
    float Mx[2][2], L[2][2];
    #pragma unroll
    for (int i = 0; i < 2; i++) {
        #pragma unroll
        for (int j = 0; j < 8; j++)
            #pragma unroll
            for (int e = 0; e < 4; e++) o[i][j][e] = 0.f;
        Mx[i][0] = Mx[i][1] = -1e30f;
        L[i][0] = L[i][1] = 0.f;
    }

    for (int mt = 0; mt < NN / 64; mt++) {
        const int st = mt & 1;
        if (mt + 1 < NN / 64) {
            issueKV(mt + 1, st ^ 1);
            CP_COMMIT();
            CP_WAIT(1);
        } else {
            CP_WAIT(0);
        }
        __syncthreads();   // loads visible to all

        const uint32_t kAddr = kvb + st * (2 * 64 * LDK) * 2 + kLane;
        const uint32_t vAddr = kvb + st * (2 * 64 * LDK) * 2 + (64 * LDK) * 2 + vLane;

        // ---- S = Q * K^T ----
        float s[2][8][4];
        #pragma unroll
        for (int i = 0; i < 2; i++)
            #pragma unroll
            for (int j = 0; j < 8; j++)
                #pragma unroll
                for (int e = 0; e < 4; e++) s[i][j][e] = 0.f;

        #pragma unroll
        for (int ks16 = 0; ks16 < 4; ks16++) {
            uint32_t a[2][4];
            ldsm4t(a[0], qb + qLane + ks16 * 16 * LDQ * 2);
            ldsm4t(a[1], qb + qLane + ks16 * 16 * LDQ * 2 + 32);
            #pragma unroll
            for (int jj = 0; jj < 4; jj++) {
                uint32_t bf[4];
                ldsm4t(bf, kAddr + ks16 * 16 * LDK * 2 + jj * 32);
                mma16816(s[0][2 * jj],     a[0], bf[0], bf[1]);
                mma16816(s[0][2 * jj + 1], a[0], bf[2], bf[3]);
                mma16816(s[1][2 * jj],     a[1], bf[0], bf[1]);
                mma16816(s[1][2 * jj + 1], a[1], bf[2], bf[3]);
            }
        }

        // ---- online softmax ----
        #pragma unroll
        for (int i = 0; i < 2; i++) {
            #pragma unroll
            for (int rh = 0; rh < 2; rh++) {
                float tm = -1e30f;
                #pragma unroll
                for (int j = 0; j < 8; j++)
                    tm = fmaxf(tm, fmaxf(s[i][j][2 * rh], s[i][j][2 * rh + 1]));
                tm = fmaxf(tm, __shfl_xor_sync(0xffffffffu, tm, 1));
                tm = fmaxf(tm, __shfl_xor_sync(0xffffffffu, tm, 2));
                float nM = fmaxf(Mx[i][rh], tm);
                float corr = __expf(Mx[i][rh] - nM);
                Mx[i][rh] = nM;
                float ls = 0.f;
                #pragma unroll
                for (int j = 0; j < 8; j++) {
                    float p0 = __expf(s[i][j][2 * rh] - nM);
                    float p1 = __expf(s[i][j][2 * rh + 1] - nM);
                    s[i][j][2 * rh] = p0;
                    s[i][j][2 * rh + 1] = p1;
                    ls += p0 + p1;
                }
                ls += __shfl_xor_sync(0xffffffffu, ls, 1);
                ls += __shfl_xor_sync(0xffffffffu, ls, 2);
                L[i][rh] = L[i][rh] * corr + ls;
                #pragma unroll
                for (int j = 0; j < 8; j++) {
                    o[i][j][2 * rh]     *= corr;
                    o[i][j][2 * rh + 1] *= corr;
                }
            }
        }

        // ---- O += P * V^T ----
        #pragma unroll
        for (int ms2 = 0; ms2 < 4; ms2++) {
            uint32_t aP[2][4];
            #pragma unroll
            for (int i = 0; i < 2; i++) {
                aP[i][0] = pk(s[i][2 * ms2][0],     s[i][2 * ms2][1]);
                aP[i][1] = pk(s[i][2 * ms2][2],     s[i][2 * ms2][3]);
                aP[i][2] = pk(s[i][2 * ms2 + 1][0], s[i][2 * ms2 + 1][1]);
                aP[i][3] = pk(s[i][2 * ms2 + 1][2], s[i][2 * ms2 + 1][3]);
            }
            #pragma unroll
            for (int jj = 0; jj < 4; jj++) {
                uint32_t bf[4];
                ldsm4(bf, vAddr + jj * 16 * LDK * 2 + ms2 * 32);
                mma16816(o[0][2 * jj],     aP[0], bf[0], bf[1]);
                mma16816(o[0][2 * jj + 1], aP[0], bf[2], bf[3]);
                mma16816(o[1][2 * jj],     aP[1], bf[0], bf[1]);
                mma16816(o[1][2 * jj + 1], aP[1], bf[2], bf[3]);
            }
        }
        __syncthreads();   // all warps done with this stage before it is refilled
    }

    // ---- epilogue: smem transpose -> coalesced fp16 stores ----
    __half* os = smh;   // reuse: [128 n][LDO d]
    #pragma unroll
    for (int i = 0; i < 2; i++) {
        float inv0 = 1.f / L[i][0];
        float inv1 = 1.f / L[i][1];
        int rl = rowbase + 16 * i + g;
        #pragma unroll
        for (int j = 0; j < 8; j++) {
            int d = 8 * j + 2 * t;
            *(uint32_t*)&os[rl * LDO + d]       = pk(o[i][j][0] * inv0, o[i][j][1] * inv0);
            *(uint32_t*)&os[(rl + 8) * LDO + d] = pk(o[i][j][2] * inv1, o[i][j][3] * inv1);
        }
    }
    __syncthreads();
    {
        const int d = tid >> 1, seg = (tid & 1) * 64;
        __half* dst = outh + ((size_t)b * CH + h * HD + d) * NN + n0 + seg;
        #pragma unroll
        for (int c8 = 0; c8 < 8; c8++) {
            __half tmp[8];
            #pragma unroll
            for (int r = 0; r < 8; r++)
                tmp[r] = os[(seg + c8 * 8 + r) * LDO + d];
            *(uint4*)&dst[c8 * 8] = *(uint4*)tmp;
        }
    }
}

// ---------------------------------------------------------------------------
// GroupNorm two-pass (deterministic, full-chip parallel)
// ---------------------------------------------------------------------------
__global__ __launch_bounds__(256) void gn_stat(const float* __restrict__ p)
{
    const int bg = blockIdx.x >> 3, sp = blockIdx.x & 7;
    const float4* p4 = (const float4*)(p + (size_t)bg * CPG * NN) + sp * 2048;
    float sum = 0.f, ss = 0.f;
    for (int i = threadIdx.x; i < 2048; i += 256) {
        float4 x = p4[i];
        sum += x.x + x.y + x.z + x.w;
        ss  += x.x * x.x + x.y * x.y + x.z * x.z + x.w * x.w;
    }
    #pragma unroll
    for (int off = 16; off; off >>= 1) {
        sum += __shfl_xor_sync(0xffffffffu, sum, off);
        ss  += __shfl_xor_sync(0xffffffffu, ss, off);
    }
    __shared__ float rs[8], rq[8];
    const int warp = threadIdx.x >> 5;
    if ((threadIdx.x & 31) == 0) { rs[warp] = sum; rq[warp] = ss; }
    __syncthreads();
    if (threadIdx.x == 0) {
        float s = 0.f, q = 0.f;
        #pragma unroll
        for (int w = 0; w < 8; w++) { s += rs[w]; q += rq[w]; }
        g_part[blockIdx.x * 2]     = s;
        g_part[blockIdx.x * 2 + 1] = q;
    }
}

__global__ __launch_bounds__(256) void gn_apply(
    const float* __restrict__ p, const float* __restrict__ x,
    const float* __restrict__ gamma, const float* __restrict__ beta,
    float* __restrict__ out)
{
    const int bg = blockIdx.x >> 3, sp = blockIdx.x & 7;
    float sum = 0.f, ss = 0.f;
    #pragma unroll
    for (int i = 0; i < 8; i++) {
        sum += g_part[(bg * 8 + i) * 2];
        ss  += g_part[(bg * 8 + i) * 2 + 1];
    }
    const float invn = 1.f / 65536.f;
    const float mean = sum * invn;
    const float inv  = rsqrtf(ss * invn - mean * mean + GN_EPS);
    const int grp = bg & 7;

    const size_t base = (size_t)bg * CPG * NN;
    const float4* p4 = (const float4*)(p + base) + sp * 2048;
    const float4* x4 = (const float4*)(x + base) + sp * 2048;
    float4*       o4 = (float4*)(out + base) + sp * 2048;

    for (int i = threadIdx.x; i < 2048; i += 256) {
        int f = sp * 2048 + i;
        int c = grp * CPG + (f >> 8);
        float ga = gamma[c] * inv, be = beta[c];
        float4 pv = p4[i], xv = x4[i], r;
        r.x = (pv.x - mean) * ga + be + xv.x;
        r.y = (pv.y - mean) * ga + be + xv.y;
        r.z = (pv.z - mean) * ga + be + xv.z;
        r.w = (pv.w - mean) * ga + be + xv.w;
        o4[i] = r;
    }
}

// ---------------------------------------------------------------------------
extern "C" void kernel_launch(void* const* d_in, const int* in_sizes, int n_in,
                              void* d_out, int out_size)
{
    const float* x      = (const float*)d_in[0];
    const float* w_qkv  = (const float*)d_in[1];
    const float* w_proj = (const float*)d_in[2];
    const float* gamma  = (const float*)d_in[3];
    const float* beta   = (const float*)d_in[4];
    float* out = (float*)d_out;

    __half* qkvh; cudaGetSymbolAddress((void**)&qkvh, g_qkvh);
    __half* atth; cudaGetSymbolAddress((void**)&atth, g_atth);
    float*  proj; cudaGetSymbolAddress((void**)&proj, g_proj);

    static bool attr_set = false;
    if (!attr_set) {
        cudaFuncSetAttribute(attn_h,
            cudaFuncAttributeMaxDynamicSharedMemorySize, ATT_SMEM);
        attr_set = true;
    }

    // 1) QKV projection -> fp16, Q pre-scaled by 0.125
    gemm_h<float, __half, true><<<dim3(NN / 128, (3 * CH) / 128, BATCH), 256>>>(
        w_qkv, x, qkvh, 3 * CH, NN, CH);

    // 2) Fused flash attention (fp16 in/out)
    attn_h<<<dim3(NN / 128, NH, BATCH), 128, ATT_SMEM>>>(qkvh, atth);

    // 3) Output projection: fp16 B -> fp32 C
    gemm_h<__half, float, false><<<dim3(NN / 128, CH / 128, BATCH), 256>>>(
        w_proj, atth, proj, CH, NN, CH);

    // 4) GroupNorm + affine + residual (two-pass)
    gn_stat<<<512, 256>>>(proj);
    gn_apply<<<512, 256>>>(proj, x, gamma, beta, out);
}

// round 8
// speedup vs baseline: 10.4712x; 1.2176x over previous
#include <cuda_runtime.h>
#include <cuda_fp16.h>
#include <math.h>
#include <stdint.h>

#define BATCH 8
#define CH    512
#define NN    1024
#define NH    8
#define HD    64
#define CPG   64
#define GN_EPS 1e-5f

// fp16 scratch
__device__ __half g_w16[(size_t)3 * CH * CH];            // w_qkv fp16
__device__ __half g_wp16[(size_t)CH * CH];               // w_proj fp16
__device__ __half g_x16[(size_t)BATCH * CH * NN];        // x fp16
__device__ __half g_qkvh[(size_t)BATCH * 3 * CH * NN];
__device__ __half g_atth[(size_t)BATCH * CH * NN];
__device__ __half g_projh[(size_t)BATCH * CH * NN];
__device__ float  g_part[64 * 8 * 2];

// ---------------------------------------------------------------------------
// helpers
// ---------------------------------------------------------------------------
__device__ __forceinline__ uint32_t smem_u32(const void* p) {
    uint32_t a;
    asm("{ .reg .u64 t; cvta.to.shared.u64 t, %1; cvt.u32.u64 %0, t; }" : "=r"(a) : "l"(p));
    return a;
}
__device__ __forceinline__ uint32_t pk(float x, float y) {
    __half2 h = __floats2half2_rn(x, y);
    return *(uint32_t*)&h;
}
__device__ __forceinline__ void mma16816(float* c, const uint32_t* a,
                                         uint32_t b0, uint32_t b1) {
    asm volatile(
        "mma.sync.aligned.m16n8k16.row.col.f32.f16.f16.f32 "
        "{%0,%1,%2,%3},{%4,%5,%6,%7},{%8,%9},{%0,%1,%2,%3};"
        : "+f"(c[0]), "+f"(c[1]), "+f"(c[2]), "+f"(c[3])
        : "r"(a[0]), "r"(a[1]), "r"(a[2]), "r"(a[3]), "r"(b0), "r"(b1));
}
__device__ __forceinline__ void ldsm4(uint32_t* r, uint32_t addr) {
    asm volatile("ldmatrix.sync.aligned.m8n8.x4.shared.b16 {%0,%1,%2,%3}, [%4];"
        : "=r"(r[0]), "=r"(r[1]), "=r"(r[2]), "=r"(r[3]) : "r"(addr));
}
__device__ __forceinline__ void ldsm4t(uint32_t* r, uint32_t addr) {
    asm volatile("ldmatrix.sync.aligned.m8n8.x4.trans.shared.b16 {%0,%1,%2,%3}, [%4];"
        : "=r"(r[0]), "=r"(r[1]), "=r"(r[2]), "=r"(r[3]) : "r"(addr));
}
__device__ __forceinline__ void cp_async16(uint32_t dst, const void* src) {
    asm volatile("cp.async.ca.shared.global [%0], [%1], 16;" :: "r"(dst), "l"(src));
}
#define CP_COMMIT() asm volatile("cp.async.commit_group;" ::: "memory")
#define CP_WAIT(n)  asm volatile("cp.async.wait_group %0;" :: "n"(n) : "memory")

// ---------------------------------------------------------------------------
// fp32 -> fp16 conversion (grid-stride, vectorized)
// ---------------------------------------------------------------------------
__global__ __launch_bounds__(256) void cvt_h(const float* __restrict__ s,
                                             __half* __restrict__ d, int n4)
{
    for (int i = blockIdx.x * 256 + threadIdx.x; i < n4; i += gridDim.x * 256) {
        float4 v = *(const float4*)&s[i * 4];
        *(uint2*)&d[i * 4] = make_uint2(pk(v.x, v.y), pk(v.z, v.w));
    }
}

// ---------------------------------------------------------------------------
// all-fp16 cp.async 3-stage GEMM: C[bz](MxN) = A(MxK) * B[bz](KxN)
// Block 128x128, 8 warps, warp tile 32x64, k-tile 32.
// ---------------------------------------------------------------------------
#define LDA 40
#define LDB 136
#define STG_A (128 * LDA)
#define STG_B (32 * LDB)
#define STG_H (STG_A + STG_B)
#define GSMEM (3 * STG_H * 2)

template<typename TC, bool SCALEQ>
__global__ __launch_bounds__(256) void gemm_a(
    const __half* __restrict__ A, const __half* __restrict__ Bg,
    TC* __restrict__ Cg, int M, int N, int K)
{
    extern __shared__ __half sh[];

    const int bz = blockIdx.z;
    const __half* Bp = Bg + (size_t)bz * K * N;
    TC*           Cp = Cg + (size_t)bz * M * N;

    const int tid = threadIdx.x;
    const int warp = tid >> 5, lane = tid & 31;
    const int wm = warp >> 1, wn = warp & 1;
    const int g = lane >> 2, t = lane & 3;
    const int row0 = blockIdx.y * 128;
    const int col0 = blockIdx.x * 128;
    const uint32_t sb = smem_u32(sh);
    const int nk = K / 32;

    auto issue = [&](int kt, int st) {
        const uint32_t sau = sb + st * STG_H * 2;
        const uint32_t sbu = sau + STG_A * 2;
        #pragma unroll
        for (int i = 0; i < 2; i++) {
            int idx = tid + i * 256;
            int r = idx >> 2, ch = idx & 3;
            cp_async16(sau + (r * LDA + ch * 8) * 2,
                       A + (size_t)(row0 + r) * K + kt * 32 + ch * 8);
        }
        #pragma unroll
        for (int i = 0; i < 2; i++) {
            int idx = tid + i * 256;
            int r = idx >> 4, ch = idx & 15;
            cp_async16(sbu + (r * LDB + ch * 8) * 2,
                       Bp + (size_t)(kt * 32 + r) * N + col0 + ch * 8);
        }
        CP_COMMIT();
    };

    float acc[2][8][4];
    #pragma unroll
    for (int i = 0; i < 2; i++)
        #pragma unroll
        for (int j = 0; j < 8; j++)
            #pragma unroll
            for (int e = 0; e < 4; e++) acc[i][j][e] = 0.f;

    issue(0, 0);
    issue(1, 1);

    const uint32_t aLane = (((wm * 32 + (lane & 15)) * LDA) + 8 * (lane >> 4)) * 2;
    const uint32_t bLane = ((((lane & 7) + 8 * ((lane >> 3) & 1)) * LDB)
                            + wn * 64 + 8 * (lane >> 4)) * 2;

    for (int kt = 0; kt < nk; kt++) {
        const int st = kt % 3;
        if (kt + 1 < nk) { CP_WAIT(1); } else { CP_WAIT(0); }
        __syncthreads();
        if (kt + 2 < nk) issue(kt + 2, (kt + 2) % 3);

        const uint32_t aAddr = sb + st * STG_H * 2 + aLane;
        const uint32_t bAddr = sb + st * STG_H * 2 + STG_A * 2 + bLane;
        #pragma unroll
        for (int ks = 0; ks < 2; ks++) {
            uint32_t a[2][4];
            ldsm4(a[0], aAddr + ks * 32);
            ldsm4(a[1], aAddr + ks * 32 + 16 * LDA * 2);
            #pragma unroll
            for (int jj = 0; jj < 4; jj++) {
                uint32_t b[4];
                ldsm4t(b, bAddr + ks * 16 * LDB * 2 + jj * 32);
                mma16816(acc[0][2 * jj],     a[0], b[0], b[1]);
                mma16816(acc[0][2 * jj + 1], a[0], b[2], b[3]);
                mma16816(acc[1][2 * jj],     a[1], b[0], b[1]);
                mma16816(acc[1][2 * jj + 1], a[1], b[2], b[3]);
            }
        }
    }

    // Q rows get 0.125 * log2(e) folded (attention uses exp2)
    const float cs = (SCALEQ && row0 < 512) ? 0.125f * 1.44269504f : 1.f;
    #pragma unroll
    for (int i = 0; i < 2; i++) {
        int r = row0 + wm * 32 + 16 * i + g;
        #pragma unroll
        for (int j = 0; j < 8; j++) {
            int c = col0 + wn * 64 + 8 * j + 2 * t;
            if constexpr (sizeof(TC) == 2) {
                *(uint32_t*)&Cp[(size_t)r * N + c] =
                    pk(acc[i][j][0] * cs, acc[i][j][1] * cs);
                *(uint32_t*)&Cp[(size_t)(r + 8) * N + c] =
                    pk(acc[i][j][2] * cs, acc[i][j][3] * cs);
            } else {
                *(float2*)&Cp[(size_t)r * N + c] =
                    make_float2(acc[i][j][0] * cs, acc[i][j][1] * cs);
                *(float2*)&Cp[(size_t)(r + 8) * N + c] =
                    make_float2(acc[i][j][2] * cs, acc[i][j][3] * cs);
            }
        }
    }
}

// ---------------------------------------------------------------------------
// Fused flash attention, fp16 in/out, cp.async double-buffered K/V, exp2.
// ---------------------------------------------------------------------------
#define LDQ 136
#define LDK 72
#define LDO 72
#define ATT_SMEM ((64 * LDQ + 4 * 64 * LDK) * 2)

__global__ __launch_bounds__(128) void attn_h(
    const __half* __restrict__ qkv, __half* __restrict__ outh)
{
    extern __shared__ __half smh[];
    __half* qs = smh;
    __half* kv = smh + 64 * LDQ;

    const int b = blockIdx.z, h = blockIdx.y;
    const int n0 = blockIdx.x * 128;
    const int tid = threadIdx.x, warp = tid >> 5, lane = tid & 31;
    const int g = lane >> 2, t = lane & 3;
    const int rowbase = warp * 32;

    const __half* q = qkv + (((size_t)b * 3 + 0) * NH + h) * HD * NN;
    const __half* k = qkv + (((size_t)b * 3 + 1) * NH + h) * HD * NN;
    const __half* v = qkv + (((size_t)b * 3 + 2) * NH + h) * HD * NN;

    const uint32_t qb  = smem_u32(qs);
    const uint32_t kvb = smem_u32(kv);
    const uint32_t qLane = ((((lane & 7) + 8 * (lane >> 4)) * LDQ)
                            + rowbase + 8 * ((lane >> 3) & 1)) * 2;
    const uint32_t kLane = ((((lane & 7) + 8 * ((lane >> 3) & 1)) * LDK)
                            + 8 * (lane >> 4)) * 2;
    const uint32_t vLane = ((((lane & 7) + 8 * (lane >> 4)) * LDK)
                            + 8 * ((lane >> 3) & 1)) * 2;

    auto issueKV = [&](int mt, int st) {
        const int m0 = mt * 64;
        const uint32_t kd = kvb + st * (2 * 64 * LDK) * 2;
        const uint32_t vd = kd + (64 * LDK) * 2;
        #pragma unroll
        for (int i = 0; i < 4; i++) {
            int idx = tid + i * 128;
            int d = idx >> 3, ch = idx & 7;
            cp_async16(kd + (d * LDK + ch * 8) * 2, k + (size_t)d * NN + m0 + ch * 8);
            cp_async16(vd + (d * LDK + ch * 8) * 2, v + (size_t)d * NN + m0 + ch * 8);
        }
    };

    #pragma unroll
    for (int i = 0; i < 8; i++) {
        int idx = tid + i * 128;
        int d = idx >> 4, ch = idx & 15;
        cp_async16(qb + (d * LDQ + ch * 8) * 2, q + (size_t)d * NN + n0 + ch * 8);
    }
    issueKV(0, 0);
    CP_COMMIT();

    float o[2][8][4];
    float Mx[2][2], L[2][2];
    #pragma unroll
    for (int i = 0; i < 2; i++) {
        #pragma unroll
        for (int j = 0; j < 8; j++)
            #pragma unroll
            for (int e = 0; e < 4; e++) o[i][j][e] = 0.f;
        Mx[i][0] = Mx[i][1] = -1e30f;
        L[i][0] = L[i][1] = 0.f;
    }

    for (int mt = 0; mt < NN / 64; mt++) {
        const int st = mt & 1;
        if (mt + 1 < NN / 64) {
            issueKV(mt + 1, st ^ 1);
            CP_COMMIT();
            CP_WAIT(1);
        } else {
            CP_WAIT(0);
        }
        __syncthreads();

        const uint32_t kAddr = kvb + st * (2 * 64 * LDK) * 2 + kLane;
        const uint32_t vAddr = kvb + st * (2 * 64 * LDK) * 2 + (64 * LDK) * 2 + vLane;

        float s[2][8][4];
        #pragma unroll
        for (int i = 0; i < 2; i++)
            #pragma unroll
            for (int j = 0; j < 8; j++)
                #pragma unroll
                for (int e = 0; e < 4; e++) s[i][j][e] = 0.f;

        #pragma unroll
        for (int ks16 = 0; ks16 < 4; ks16++) {
            uint32_t a[2][4];
            ldsm4t(a[0], qb + qLane + ks16 * 16 * LDQ * 2);
            ldsm4t(a[1], qb + qLane + ks16 * 16 * LDQ * 2 + 32);
            #pragma unroll
            for (int jj = 0; jj < 4; jj++) {
                uint32_t bf[4];
                ldsm4t(bf, kAddr + ks16 * 16 * LDK * 2 + jj * 32);
                mma16816(s[0][2 * jj],     a[0], bf[0], bf[1]);
                mma16816(s[0][2 * jj + 1], a[0], bf[2], bf[3]);
                mma16816(s[1][2 * jj],     a[1], bf[0], bf[1]);
                mma16816(s[1][2 * jj + 1], a[1], bf[2], bf[3]);
            }
        }

        #pragma unroll
        for (int i = 0; i < 2; i++) {
            #pragma unroll
            for (int rh = 0; rh < 2; rh++) {
                float tm = -1e30f;
                #pragma unroll
                for (int j = 0; j < 8; j++)
                    tm = fmaxf(tm, fmaxf(s[i][j][2 * rh], s[i][j][2 * rh + 1]));
                tm = fmaxf(tm, __shfl_xor_sync(0xffffffffu, tm, 1));
                tm = fmaxf(tm, __shfl_xor_sync(0xffffffffu, tm, 2));
                float nM = fmaxf(Mx[i][rh], tm);
                float corr = exp2f(Mx[i][rh] - nM);
                Mx[i][rh] = nM;
                float ls = 0.f;
                #pragma unroll
                for (int j = 0; j < 8; j++) {
                    float p0 = exp2f(s[i][j][2 * rh] - nM);
                    float p1 = exp2f(s[i][j][2 * rh + 1] - nM);
                    s[i][j][2 * rh] = p0;
                    s[i][j][2 * rh + 1] = p1;
                    ls += p0 + p1;
                }
                ls += __shfl_xor_sync(0xffffffffu, ls, 1);
                ls += __shfl_xor_sync(0xffffffffu, ls, 2);
                L[i][rh] = L[i][rh] * corr + ls;
                #pragma unroll
                for (int j = 0; j < 8; j++) {
                    o[i][j][2 * rh]     *= corr;
                    o[i][j][2 * rh + 1] *= corr;
                }
            }
        }

        #pragma unroll
        for (int ms2 = 0; ms2 < 4; ms2++) {
            uint32_t aP[2][4];
            #pragma unroll
            for (int i = 0; i < 2; i++) {
                aP[i][0] = pk(s[i][2 * ms2][0],     s[i][2 * ms2][1]);
                aP[i][1] = pk(s[i][2 * ms2][2],     s[i][2 * ms2][3]);
                aP[i][2] = pk(s[i][2 * ms2 + 1][0], s[i][2 * ms2 + 1][1]);
                aP[i][3] = pk(s[i][2 * ms2 + 1][2], s[i][2 * ms2 + 1][3]);
            }
            #pragma unroll
            for (int jj = 0; jj < 4; jj++) {
                uint32_t bf[4];
                ldsm4(bf, vAddr + jj * 16 * LDK * 2 + ms2 * 32);
                mma16816(o[0][2 * jj],     aP[0], bf[0], bf[1]);
                mma16816(o[0][2 * jj + 1], aP[0], bf[2], bf[3]);
                mma16816(o[1][2 * jj],     aP[1], bf[0], bf[1]);
                mma16816(o[1][2 * jj + 1], aP[1], bf[2], bf[3]);
            }
        }
        __syncthreads();
    }

    __half* os = smh;
    #pragma unroll
    for (int i = 0; i < 2; i++) {
        float inv0 = 1.f / L[i][0];
        float inv1 = 1.f / L[i][1];
        int rl = rowbase + 16 * i + g;
        #pragma unroll
        for (int j = 0; j < 8; j++) {
            int d = 8 * j + 2 * t;
            *(uint32_t*)&os[rl * LDO + d]       = pk(o[i][j][0] * inv0, o[i][j][1] * inv0);
            *(uint32_t*)&os[(rl + 8) * LDO + d] = pk(o[i][j][2] * inv1, o[i][j][3] * inv1);
        }
    }
    __syncthreads();
    {
        const int d = tid >> 1, seg = (tid & 1) * 64;
        __half* dst = outh + ((size_t)b * CH + h * HD + d) * NN + n0 + seg;
        #pragma unroll
        for (int c8 = 0; c8 < 8; c8++) {
            __half tmp[8];
            #pragma unroll
            for (int r = 0; r < 8; r++)
                tmp[r] = os[(seg + c8 * 8 + r) * LDO + d];
            *(uint4*)&dst[c8 * 8] = *(uint4*)tmp;
        }
    }
}

// ---------------------------------------------------------------------------
// GroupNorm two-pass over fp16 proj
// ---------------------------------------------------------------------------
__global__ __launch_bounds__(256) void gn_stat(const __half* __restrict__ p)
{
    const int bg = blockIdx.x >> 3, sp = blockIdx.x & 7;
    const uint4* p8 = (const uint4*)(p + (size_t)bg * CPG * NN) + sp * 1024;
    float sum = 0.f, ss = 0.f;
    #pragma unroll
    for (int it = 0; it < 4; it++) {
        uint4 u = p8[threadIdx.x + it * 256];
        const __half2* hp = (const __half2*)&u;
        #pragma unroll
        for (int j = 0; j < 4; j++) {
            float2 f = __half22float2(hp[j]);
            sum += f.x + f.y;
            ss  += f.x * f.x + f.y * f.y;
        }
    }
    #pragma unroll
    for (int off = 16; off; off >>= 1) {
        sum += __shfl_xor_sync(0xffffffffu, sum, off);
        ss  += __shfl_xor_sync(0xffffffffu, ss, off);
    }
    __shared__ float rs[8], rq[8];
    const int warp = threadIdx.x >> 5;
    if ((threadIdx.x & 31) == 0) { rs[warp] = sum; rq[warp] = ss; }
    __syncthreads();
    if (threadIdx.x == 0) {
        float s = 0.f, q = 0.f;
        #pragma unroll
        for (int w = 0; w < 8; w++) { s += rs[w]; q += rq[w]; }
        g_part[blockIdx.x * 2]     = s;
        g_part[blockIdx.x * 2 + 1] = q;
    }
}

__global__ __launch_bounds__(256) void gn_apply(
    const __half* __restrict__ p, const float* __restrict__ x,
    const float* __restrict__ gamma, const float* __restrict__ beta,
    float* __restrict__ out)
{
    const int bg = blockIdx.x >> 3, sp = blockIdx.x & 7;
    float sum = 0.f, ss = 0.f;
    #pragma unroll
    for (int i = 0; i < 8; i++) {
        sum += g_part[(bg * 8 + i) * 2];
        ss  += g_part[(bg * 8 + i) * 2 + 1];
    }
    const float invn = 1.f / 65536.f;
    const float mean = sum * invn;
    const float inv  = rsqrtf(ss * invn - mean * mean + GN_EPS);
    const int grp = bg & 7;

    const size_t base = (size_t)bg * CPG * NN;
    const uint4*  p8 = (const uint4*)(p + base) + sp * 1024;
    const float4* x4 = (const float4*)(x + base) + sp * 2048;
    float4*       o4 = (float4*)(out + base) + sp * 2048;

    #pragma unroll
    for (int it = 0; it < 4; it++) {
        int idx = threadIdx.x + it * 256;
        int c = grp * CPG + sp * 8 + (idx >> 7);
        float ga = gamma[c] * inv, be = beta[c];
        uint4 u = p8[idx];
        const __half2* hp = (const __half2*)&u;
        float4 xa = x4[2 * idx], xb = x4[2 * idx + 1];
        float2 f0 = __half22float2(hp[0]), f1 = __half22float2(hp[1]);
        float2 f2 = __half22float2(hp[2]), f3 = __half22float2(hp[3]);
        float4 ra, rb;
        ra.x = (f0.x - mean) * ga + be + xa.x;
        ra.y = (f0.y - mean) * ga + be + xa.y;
        ra.z = (f1.x - mean) * ga + be + xa.z;
        ra.w = (f1.y - mean) * ga + be + xa.w;
        rb.x = (f2.x - mean) * ga + be + xb.x;
        rb.y = (f2.y - mean) * ga + be + xb.y;
        rb.z = (f3.x - mean) * ga + be + xb.z;
        rb.w = (f3.y - mean) * ga + be + xb.w;
        o4[2 * idx]     = ra;
        o4[2 * idx + 1] = rb;
    }
}

// ---------------------------------------------------------------------------
extern "C" void kernel_launch(void* const* d_in, const int* in_sizes, int n_in,
                              void* d_out, int out_size)
{
    const float* x      = (const float*)d_in[0];
    const float* w_qkv  = (const float*)d_in[1];
    const float* w_proj = (const float*)d_in[2];
    const float* gamma  = (const float*)d_in[3];
    const float* beta   = (const float*)d_in[4];
    float* out = (float*)d_out;

    __half *w16, *wp16, *x16, *qkvh, *atth, *projh;
    cudaGetSymbolAddress((void**)&w16,   g_w16);
    cudaGetSymbolAddress((void**)&wp16,  g_wp16);
    cudaGetSymbolAddress((void**)&x16,   g_x16);
    cudaGetSymbolAddress((void**)&qkvh,  g_qkvh);
    cudaGetSymbolAddress((void**)&atth,  g_atth);
    cudaGetSymbolAddress((void**)&projh, g_projh);

    static bool attr_set = false;
    if (!attr_set) {
        cudaFuncSetAttribute(attn_h,
            cudaFuncAttributeMaxDynamicSharedMemorySize, ATT_SMEM);
        cudaFuncSetAttribute((const void*)gemm_a<__half, true>,
            cudaFuncAttributeMaxDynamicSharedMemorySize, GSMEM);
        cudaFuncSetAttribute((const void*)gemm_a<__half, false>,
            cudaFuncAttributeMaxDynamicSharedMemorySize, GSMEM);
        attr_set = true;
    }

    // 0) fp32 -> fp16 conversions
    cvt_h<<<192, 256>>>(w_qkv, w16, (3 * CH * CH) / 4);
    cvt_h<<<64,  256>>>(w_proj, wp16, (CH * CH) / 4);
    cvt_h<<<1024, 256>>>(x, x16, (BATCH * CH * NN) / 4);

    // 1) QKV projection (Q rows scaled by 0.125*log2e)
    gemm_a<__half, true><<<dim3(NN / 128, (3 * CH) / 128, BATCH), 256, GSMEM>>>(
        w16, x16, qkvh, 3 * CH, NN, CH);

    // 2) Fused flash attention
    attn_h<<<dim3(NN / 128, NH, BATCH), 128, ATT_SMEM>>>(qkvh, atth);

    // 3) Output projection -> fp16
    gemm_a<__half, false><<<dim3(NN / 128, CH / 128, BATCH), 256, GSMEM>>>(
        wp16, atth, projh, CH, NN, CH);

    // 4) GroupNorm + affine + residual
    gn_stat<<<512, 256>>>(projh);
    gn_apply<<<512, 256>>>(projh, x, gamma, beta, out);
}

// round 9
// speedup vs baseline: 10.6145x; 1.0137x over previous
#include <cuda_runtime.h>
#include <cuda_fp16.h>
#include <math.h>
#include <stdint.h>

#define BATCH 8
#define CH    512
#define NN    1024
#define NH    8
#define HD    64
#define CPG   64
#define GN_EPS 1e-5f

// fp16 scratch
__device__ __half g_w16[(size_t)3 * CH * CH];
__device__ __half g_wp16[(size_t)CH * CH];
__device__ __half g_x16[(size_t)BATCH * CH * NN];
__device__ __half g_qkvh[(size_t)BATCH * 3 * CH * NN];
__device__ __half g_atth[(size_t)BATCH * CH * NN];
__device__ __half g_projh[(size_t)BATCH * CH * NN];
__device__ float  g_part[64 * 8 * 2];

// ---------------------------------------------------------------------------
// helpers
// ---------------------------------------------------------------------------
__device__ __forceinline__ uint32_t smem_u32(const void* p) {
    uint32_t a;
    asm("{ .reg .u64 t; cvta.to.shared.u64 t, %1; cvt.u32.u64 %0, t; }" : "=r"(a) : "l"(p));
    return a;
}
__device__ __forceinline__ uint32_t pk(float x, float y) {
    __half2 h = __floats2half2_rn(x, y);
    return *(uint32_t*)&h;
}
__device__ __forceinline__ void mma16816(float* c, const uint32_t* a,
                                         uint32_t b0, uint32_t b1) {
    asm volatile(
        "mma.sync.aligned.m16n8k16.row.col.f32.f16.f16.f32 "
        "{%0,%1,%2,%3},{%4,%5,%6,%7},{%8,%9},{%0,%1,%2,%3};"
        : "+f"(c[0]), "+f"(c[1]), "+f"(c[2]), "+f"(c[3])
        : "r"(a[0]), "r"(a[1]), "r"(a[2]), "r"(a[3]), "r"(b0), "r"(b1));
}
__device__ __forceinline__ void ldsm4(uint32_t* r, uint32_t addr) {
    asm volatile("ldmatrix.sync.aligned.m8n8.x4.shared.b16 {%0,%1,%2,%3}, [%4];"
        : "=r"(r[0]), "=r"(r[1]), "=r"(r[2]), "=r"(r[3]) : "r"(addr));
}
__device__ __forceinline__ void ldsm4t(uint32_t* r, uint32_t addr) {
    asm volatile("ldmatrix.sync.aligned.m8n8.x4.trans.shared.b16 {%0,%1,%2,%3}, [%4];"
        : "=r"(r[0]), "=r"(r[1]), "=r"(r[2]), "=r"(r[3]) : "r"(addr));
}
__device__ __forceinline__ void cp_async16(uint32_t dst, const void* src) {
    asm volatile("cp.async.ca.shared.global [%0], [%1], 16;" :: "r"(dst), "l"(src));
}
#define CP_COMMIT() asm volatile("cp.async.commit_group;" ::: "memory")
#define CP_WAIT(n)  asm volatile("cp.async.wait_group %0;" :: "n"(n) : "memory")

// ---------------------------------------------------------------------------
// single-launch fp32 -> fp16 conversion of all three tensors
// ---------------------------------------------------------------------------
#define CVT_N1 ((3 * CH * CH) / 4)
#define CVT_N2 ((CH * CH) / 4)
#define CVT_N3 ((BATCH * CH * NN) / 4)
__global__ __launch_bounds__(256) void cvt_all(
    const float* __restrict__ w, __half* __restrict__ w16,
    const float* __restrict__ wp, __half* __restrict__ wp16,
    const float* __restrict__ x, __half* __restrict__ x16)
{
    const int total = CVT_N1 + CVT_N2 + CVT_N3;
    for (int i = blockIdx.x * 256 + threadIdx.x; i < total; i += gridDim.x * 256) {
        const float* s; __half* d; int j;
        if (i < CVT_N1)                { s = w;  d = w16;  j = i; }
        else if (i < CVT_N1 + CVT_N2)  { s = wp; d = wp16; j = i - CVT_N1; }
        else                           { s = x;  d = x16;  j = i - CVT_N1 - CVT_N2; }
        float4 v = *(const float4*)&s[(size_t)j * 4];
        *(uint2*)&d[(size_t)j * 4] = make_uint2(pk(v.x, v.y), pk(v.z, v.w));
    }
}

// ---------------------------------------------------------------------------
// all-fp16 cp.async 3-stage GEMM. CTA tile 256x128, 8 warps (4x2),
// warp tile 64x64, k-tile 32. Grid (N/128, M/256, batch).
// ---------------------------------------------------------------------------
#define LDA 40
#define LDB 136
#define STG_A (256 * LDA)
#define STG_B (32 * LDB)
#define STG_H (STG_A + STG_B)
#define GSMEM (3 * STG_H * 2)

template<typename TC, bool SCALEQ>
__global__ __launch_bounds__(256) void gemm_a(
    const __half* __restrict__ A, const __half* __restrict__ Bg,
    TC* __restrict__ Cg, int M, int N, int K)
{
    extern __shared__ __half sh[];

    const int bz = blockIdx.z;
    const __half* Bp = Bg + (size_t)bz * K * N;
    TC*           Cp = Cg + (size_t)bz * M * N;

    const int tid = threadIdx.x;
    const int warp = tid >> 5, lane = tid & 31;
    const int wm = warp >> 1, wn = warp & 1;
    const int g = lane >> 2, t = lane & 3;
    const int row0 = blockIdx.y * 256;
    const int col0 = blockIdx.x * 128;
    const uint32_t sb = smem_u32(sh);
    const int nk = K / 32;

    auto issue = [&](int kt, int st) {
        const uint32_t sau = sb + st * STG_H * 2;
        const uint32_t sbu = sau + STG_A * 2;
        // A: 256 rows x 32 k = 1024 16B-chunks, 4/thread
        #pragma unroll
        for (int i = 0; i < 4; i++) {
            int idx = tid + i * 256;
            int r = idx >> 2, ch = idx & 3;
            cp_async16(sau + (r * LDA + ch * 8) * 2,
                       A + (size_t)(row0 + r) * K + kt * 32 + ch * 8);
        }
        // B: 32 rows x 128 n = 512 chunks, 2/thread
        #pragma unroll
        for (int i = 0; i < 2; i++) {
            int idx = tid + i * 256;
            int r = idx >> 4, ch = idx & 15;
            cp_async16(sbu + (r * LDB + ch * 8) * 2,
                       Bp + (size_t)(kt * 32 + r) * N + col0 + ch * 8);
        }
        CP_COMMIT();
    };

    float acc[4][8][4];
    #pragma unroll
    for (int i = 0; i < 4; i++)
        #pragma unroll
        for (int j = 0; j < 8; j++)
            #pragma unroll
            for (int e = 0; e < 4; e++) acc[i][j][e] = 0.f;

    issue(0, 0);
    issue(1, 1);

    const uint32_t aLane = (((wm * 64 + (lane & 15)) * LDA) + 8 * (lane >> 4)) * 2;
    const uint32_t bLane = ((((lane & 7) + 8 * ((lane >> 3) & 1)) * LDB)
                            + wn * 64 + 8 * (lane >> 4)) * 2;

    for (int kt = 0; kt < nk; kt++) {
        const int st = kt % 3;
        if (kt + 1 < nk) { CP_WAIT(1); } else { CP_WAIT(0); }
        __syncthreads();
        if (kt + 2 < nk) issue(kt + 2, (kt + 2) % 3);

        const uint32_t aAddr = sb + st * STG_H * 2 + aLane;
        const uint32_t bAddr = sb + st * STG_H * 2 + STG_A * 2 + bLane;
        #pragma unroll
        for (int ks = 0; ks < 2; ks++) {
            uint32_t a[4][4];
            #pragma unroll
            for (int mi = 0; mi < 4; mi++)
                ldsm4(a[mi], aAddr + ks * 32 + mi * 16 * LDA * 2);
            #pragma unroll
            for (int jj = 0; jj < 4; jj++) {
                uint32_t b[4];
                ldsm4t(b, bAddr + ks * 16 * LDB * 2 + jj * 32);
                #pragma unroll
                for (int mi = 0; mi < 4; mi++) {
                    mma16816(acc[mi][2 * jj],     a[mi], b[0], b[1]);
                    mma16816(acc[mi][2 * jj + 1], a[mi], b[2], b[3]);
                }
            }
        }
    }

    // Q rows get 0.125 * log2(e) folded (attention uses exp2)
    const float cs = (SCALEQ && row0 < 512) ? 0.125f * 1.44269504f : 1.f;
    #pragma unroll
    for (int mi = 0; mi < 4; mi++) {
        int r = row0 + wm * 64 + mi * 16 + g;
        #pragma unroll
        for (int j = 0; j < 8; j++) {
            int c = col0 + wn * 64 + 8 * j + 2 * t;
            if constexpr (sizeof(TC) == 2) {
                *(uint32_t*)&Cp[(size_t)r * N + c] =
                    pk(acc[mi][j][0] * cs, acc[mi][j][1] * cs);
                *(uint32_t*)&Cp[(size_t)(r + 8) * N + c] =
                    pk(acc[mi][j][2] * cs, acc[mi][j][3] * cs);
            } else {
                *(float2*)&Cp[(size_t)r * N + c] =
                    make_float2(acc[mi][j][0] * cs, acc[mi][j][1] * cs);
                *(float2*)&Cp[(size_t)(r + 8) * N + c] =
                    make_float2(acc[mi][j][2] * cs, acc[mi][j][3] * cs);
            }
        }
    }
}

// ---------------------------------------------------------------------------
// Fused flash attention, fp16 in/out, cp.async double-buffered K/V, exp2.
// (unchanged from R7)
// ---------------------------------------------------------------------------
#define LDQ 136
#define LDK 72
#define LDO 72
#define ATT_SMEM ((64 * LDQ + 4 * 64 * LDK) * 2)

__global__ __launch_bounds__(128) void attn_h(
    const __half* __restrict__ qkv, __half* __restrict__ outh)
{
    extern __shared__ __half smh[];
    __half* qs = smh;
    __half* kv = smh + 64 * LDQ;

    const int b = blockIdx.z, h = blockIdx.y;
    const int n0 = blockIdx.x * 128;
    const int tid = threadIdx.x, warp = tid >> 5, lane = tid & 31;
    const int g = lane >> 2, t = lane & 3;
    const int rowbase = warp * 32;

    const __half* q = qkv + (((size_t)b * 3 + 0) * NH + h) * HD * NN;
    const __half* k = qkv + (((size_t)b * 3 + 1) * NH + h) * HD * NN;
    const __half* v = qkv + (((size_t)b * 3 + 2) * NH + h) * HD * NN;

    const uint32_t qb  = smem_u32(qs);
    const uint32_t kvb = smem_u32(kv);
    const uint32_t qLane = ((((lane & 7) + 8 * (lane >> 4)) * LDQ)
                            + rowbase + 8 * ((lane >> 3) & 1)) * 2;
    const uint32_t kLane = ((((lane & 7) + 8 * ((lane >> 3) & 1)) * LDK)
                            + 8 * (lane >> 4)) * 2;
    const uint32_t vLane = ((((lane & 7) + 8 * (lane >> 4)) * LDK)
                            + 8 * ((lane >> 3) & 1)) * 2;

    auto issueKV = [&](int mt, int st) {
        const int m0 = mt * 64;
        const uint32_t kd = kvb + st * (2 * 64 * LDK) * 2;
        const uint32_t vd = kd + (64 * LDK) * 2;
        #pragma unroll
        for (int i = 0; i < 4; i++) {
            int idx = tid + i * 128;
            int d = idx >> 3, ch = idx & 7;
            cp_async16(kd + (d * LDK + ch * 8) * 2, k + (size_t)d * NN + m0 + ch * 8);
            cp_async16(vd + (d * LDK + ch * 8) * 2, v + (size_t)d * NN + m0 + ch * 8);
        }
    };

    #pragma unroll
    for (int i = 0; i < 8; i++) {
        int idx = tid + i * 128;
        int d = idx >> 4, ch = idx & 15;
        cp_async16(qb + (d * LDQ + ch * 8) * 2, q + (size_t)d * NN + n0 + ch * 8);
    }
    issueKV(0, 0);
    CP_COMMIT();

    float o[2][8][4];
    float Mx[2][2], L[2][2];
    #pragma unroll
    for (int i = 0; i < 2; i++) {
        #pragma unroll
        for (int j = 0; j < 8; j++)
            #pragma unroll
            for (int e = 0; e < 4; e++) o[i][j][e] = 0.f;
        Mx[i][0] = Mx[i][1] = -1e30f;
        L[i][0] = L[i][1] = 0.f;
    }

    for (int mt = 0; mt < NN / 64; mt++) {
        const int st = mt & 1;
        if (mt + 1 < NN / 64) {
            issueKV(mt + 1, st ^ 1);
            CP_COMMIT();
            CP_WAIT(1);
        } else {
            CP_WAIT(0);
        }
        __syncthreads();

        const uint32_t kAddr = kvb + st * (2 * 64 * LDK) * 2 + kLane;
        const uint32_t vAddr = kvb + st * (2 * 64 * LDK) * 2 + (64 * LDK) * 2 + vLane;

        float s[2][8][4];
        #pragma unroll
        for (int i = 0; i < 2; i++)
            #pragma unroll
            for (int j = 0; j < 8; j++)
                #pragma unroll
                for (int e = 0; e < 4; e++) s[i][j][e] = 0.f;

        #pragma unroll
        for (int ks16 = 0; ks16 < 4; ks16++) {
            uint32_t a[2][4];
            ldsm4t(a[0], qb + qLane + ks16 * 16 * LDQ * 2);
            ldsm4t(a[1], qb + qLane + ks16 * 16 * LDQ * 2 + 32);
            #pragma unroll
            for (int jj = 0; jj < 4; jj++) {
                uint32_t bf[4];
                ldsm4t(bf, kAddr + ks16 * 16 * LDK * 2 + jj * 32);
                mma16816(s[0][2 * jj],     a[0], bf[0], bf[1]);
                mma16816(s[0][2 * jj + 1], a[0], bf[2], bf[3]);
                mma16816(s[1][2 * jj],     a[1], bf[0], bf[1]);
                mma16816(s[1][2 * jj + 1], a[1], bf[2], bf[3]);
            }
        }

        #pragma unroll
        for (int i = 0; i < 2; i++) {
            #pragma unroll
            for (int rh = 0; rh < 2; rh++) {
                float tm = -1e30f;
                #pragma unroll
                for (int j = 0; j < 8; j++)
                    tm = fmaxf(tm, fmaxf(s[i][j][2 * rh], s[i][j][2 * rh + 1]));
                tm = fmaxf(tm, __shfl_xor_sync(0xffffffffu, tm, 1));
                tm = fmaxf(tm, __shfl_xor_sync(0xffffffffu, tm, 2));
                float nM = fmaxf(Mx[i][rh], tm);
                float corr = exp2f(Mx[i][rh] - nM);
                Mx[i][rh] = nM;
                float ls = 0.f;
                #pragma unroll
                for (int j = 0; j < 8; j++) {
                    float p0 = exp2f(s[i][j][2 * rh] - nM);
                    float p1 = exp2f(s[i][j][2 * rh + 1] - nM);
                    s[i][j][2 * rh] = p0;
                    s[i][j][2 * rh + 1] = p1;
                    ls += p0 + p1;
                }
                ls += __shfl_xor_sync(0xffffffffu, ls, 1);
                ls += __shfl_xor_sync(0xffffffffu, ls, 2);
                L[i][rh] = L[i][rh] * corr + ls;
                #pragma unroll
                for (int j = 0; j < 8; j++) {
                    o[i][j][2 * rh]     *= corr;
                    o[i][j][2 * rh + 1] *= corr;
                }
            }
        }

        #pragma unroll
        for (int ms2 = 0; ms2 < 4; ms2++) {
            uint32_t aP[2][4];
            #pragma unroll
            for (int i = 0; i < 2; i++) {
                aP[i][0] = pk(s[i][2 * ms2][0],     s[i][2 * ms2][1]);
                aP[i][1] = pk(s[i][2 * ms2][2],     s[i][2 * ms2][3]);
                aP[i][2] = pk(s[i][2 * ms2 + 1][0], s[i][2 * ms2 + 1][1]);
                aP[i][3] = pk(s[i][2 * ms2 + 1][2], s[i][2 * ms2 + 1][3]);
            }
            #pragma unroll
            for (int jj = 0; jj < 4; jj++) {
                uint32_t bf[4];
                ldsm4(bf, vAddr + jj * 16 * LDK * 2 + ms2 * 32);
                mma16816(o[0][2 * jj],     aP[0], bf[0], bf[1]);
                mma16816(o[0][2 * jj + 1], aP[0], bf[2], bf[3]);
                mma16816(o[1][2 * jj],     aP[1], bf[0], bf[1]);
                mma16816(o[1][2 * jj + 1], aP[1], bf[2], bf[3]);
            }
        }
        __syncthreads();
    }

    __half* os = smh;
    #pragma unroll
    for (int i = 0; i < 2; i++) {
        float inv0 = 1.f / L[i][0];
        float inv1 = 1.f / L[i][1];
        int rl = rowbase + 16 * i + g;
        #pragma unroll
        for (int j = 0; j < 8; j++) {
            int d = 8 * j + 2 * t;
            *(uint32_t*)&os[rl * LDO + d]       = pk(o[i][j][0] * inv0, o[i][j][1] * inv0);
            *(uint32_t*)&os[(rl + 8) * LDO + d] = pk(o[i][j][2] * inv1, o[i][j][3] * inv1);
        }
    }
    __syncthreads();
    {
        const int d = tid >> 1, seg = (tid & 1) * 64;
        __half* dst = outh + ((size_t)b * CH + h * HD + d) * NN + n0 + seg;
        #pragma unroll
        for (int c8 = 0; c8 < 8; c8++) {
            __half tmp[8];
            #pragma unroll
            for (int r = 0; r < 8; r++)
                tmp[r] = os[(seg + c8 * 8 + r) * LDO + d];
            *(uint4*)&dst[c8 * 8] = *(uint4*)tmp;
        }
    }
}

// ---------------------------------------------------------------------------
// GroupNorm two-pass over fp16 proj (unchanged)
// ---------------------------------------------------------------------------
__global__ __launch_bounds__(256) void gn_stat(const __half* __restrict__ p)
{
    const int bg = blockIdx.x >> 3, sp = blockIdx.x & 7;
    const uint4* p8 = (const uint4*)(p + (size_t)bg * CPG * NN) + sp * 1024;
    float sum = 0.f, ss = 0.f;
    #pragma unroll
    for (int it = 0; it < 4; it++) {
        uint4 u = p8[threadIdx.x + it * 256];
        const __half2* hp = (const __half2*)&u;
        #pragma unroll
        for (int j = 0; j < 4; j++) {
            float2 f = __half22float2(hp[j]);
            sum += f.x + f.y;
            ss  += f.x * f.x + f.y * f.y;
        }
    }
    #pragma unroll
    for (int off = 16; off; off >>= 1) {
        sum += __shfl_xor_sync(0xffffffffu, sum, off);
        ss  += __shfl_xor_sync(0xffffffffu, ss, off);
    }
    __shared__ float rs[8], rq[8];
    const int warp = threadIdx.x >> 5;
    if ((threadIdx.x & 31) == 0) { rs[warp] = sum; rq[warp] = ss; }
    __syncthreads();
    if (threadIdx.x == 0) {
        float s = 0.f, q = 0.f;
        #pragma unroll
        for (int w = 0; w < 8; w++) { s += rs[w]; q += rq[w]; }
        g_part[blockIdx.x * 2]     = s;
        g_part[blockIdx.x * 2 + 1] = q;
    }
}

__global__ __launch_bounds__(256) void gn_apply(
    const __half* __restrict__ p, const float* __restrict__ x,
    const float* __restrict__ gamma, const float* __restrict__ beta,
    float* __restrict__ out)
{
    const int bg = blockIdx.x >> 3, sp = blockIdx.x & 7;
    float sum = 0.f, ss = 0.f;
    #pragma unroll
    for (int i = 0; i < 8; i++) {
        sum += g_part[(bg * 8 + i) * 2];
        ss  += g_part[(bg * 8 + i) * 2 + 1];
    }
    const float invn = 1.f / 65536.f;
    const float mean = sum * invn;
    const float inv  = rsqrtf(ss * invn - mean * mean + GN_EPS);
    const int grp = bg & 7;

    const size_t base = (size_t)bg * CPG * NN;
    const uint4*  p8 = (const uint4*)(p + base) + sp * 1024;
    const float4* x4 = (const float4*)(x + base) + sp * 2048;
    float4*       o4 = (float4*)(out + base) + sp * 2048;

    #pragma unroll
    for (int it = 0; it < 4; it++) {
        int idx = threadIdx.x + it * 256;
        int c = grp * CPG + sp * 8 + (idx >> 7);
        float ga = gamma[c] * inv, be = beta[c];
        uint4 u = p8[idx];
        const __half2* hp = (const __half2*)&u;
        float4 xa = x4[2 * idx], xb = x4[2 * idx + 1];
        float2 f0 = __half22float2(hp[0]), f1 = __half22float2(hp[1]);
        float2 f2 = __half22float2(hp[2]), f3 = __half22float2(hp[3]);
        float4 ra, rb;
        ra.x = (f0.x - mean) * ga + be + xa.x;
        ra.y = (f0.y - mean) * ga + be + xa.y;
        ra.z = (f1.x - mean) * ga + be + xa.z;
        ra.w = (f1.y - mean) * ga + be + xa.w;
        rb.x = (f2.x - mean) * ga + be + xb.x;
        rb.y = (f2.y - mean) * ga + be + xb.y;
        rb.z = (f3.x - mean) * ga + be + xb.z;
        rb.w = (f3.y - mean) * ga + be + xb.w;
        o4[2 * idx]     = ra;
        o4[2 * idx + 1] = rb;
    }
}

// ---------------------------------------------------------------------------
extern "C" void kernel_launch(void* const* d_in, const int* in_sizes, int n_in,
                              void* d_out, int out_size)
{
    const float* x      = (const float*)d_in[0];
    const float* w_qkv  = (const float*)d_in[1];
    const float* w_proj = (const float*)d_in[2];
    const float* gamma  = (const float*)d_in[3];
    const float* beta   = (const float*)d_in[4];
    float* out = (float*)d_out;

    __half *w16, *wp16, *x16, *qkvh, *atth, *projh;
    cudaGetSymbolAddress((void**)&w16,   g_w16);
    cudaGetSymbolAddress((void**)&wp16,  g_wp16);
    cudaGetSymbolAddress((void**)&x16,   g_x16);
    cudaGetSymbolAddress((void**)&qkvh,  g_qkvh);
    cudaGetSymbolAddress((void**)&atth,  g_atth);
    cudaGetSymbolAddress((void**)&projh, g_projh);

    static bool attr_set = false;
    if (!attr_set) {
        cudaFuncSetAttribute(attn_h,
            cudaFuncAttributeMaxDynamicSharedMemorySize, ATT_SMEM);
        cudaFuncSetAttribute((const void*)gemm_a<__half, true>,
            cudaFuncAttributeMaxDynamicSharedMemorySize, GSMEM);
        cudaFuncSetAttribute((const void*)gemm_a<__half, false>,
            cudaFuncAttributeMaxDynamicSharedMemorySize, GSMEM);
        attr_set = true;
    }

    // 0) single-launch fp32 -> fp16 conversion
    cvt_all<<<1280, 256>>>(w_qkv, w16, w_proj, wp16, x, x16);

    // 1) QKV projection (Q rows scaled by 0.125*log2e)
    gemm_a<__half, true><<<dim3(NN / 128, (3 * CH) / 256, BATCH), 256, GSMEM>>>(
        w16, x16, qkvh, 3 * CH, NN, CH);

    // 2) Fused flash attention
    attn_h<<<dim3(NN / 128, NH, BATCH), 128, ATT_SMEM>>>(qkvh, atth);

    // 3) Output projection -> fp16
    gemm_a<__half, false><<<dim3(NN / 128, CH / 256, BATCH), 256, GSMEM>>>(
        wp16, atth, projh, CH, NN, CH);

    // 4) GroupNorm + affine + residual
    gn_stat<<<512, 256>>>(projh);
    gn_apply<<<512, 256>>>(projh, x, gamma, beta, out);
}